// round 2
// baseline (speedup 1.0000x reference)
#include <cuda_runtime.h>
#include <cuda_bf16.h>
#include <math.h>

#define D_MODEL 768
#define N_HEADS 12
#define HEAD_DIM 64
#define N_LAYERS 12
#define SEQ 1024
#define BATCH 4
#define ROWS (BATCH * SEQ)       // 4096
#define D_FF (4 * D_MODEL)       // 3072
#define VOCAB 50257

// ---------------- scratch (device globals; no allocation allowed) ----------------
__device__ float g_h[ROWS * D_MODEL];
__device__ float g_a[ROWS * D_MODEL];
__device__ float g_q[ROWS * D_MODEL];
__device__ float g_k[ROWS * D_MODEL];
__device__ float g_v[ROWS * D_MODEL];
__device__ float g_o[ROWS * D_MODEL];
__device__ float g_m[ROWS * D_FF];

// ---------------- embedding ----------------
__global__ void embed_kernel(const int* __restrict__ x, const float* __restrict__ wte,
                             const float* __restrict__ wpe, float* __restrict__ h) {
    int row = blockIdx.x;            // 0..4095
    int tok = x[row];
    int s = row & (SEQ - 1);
    const float* te = wte + (size_t)tok * D_MODEL;
    const float* pe = wpe + (size_t)s * D_MODEL;
    float* out = h + (size_t)row * D_MODEL;
    for (int d = threadIdx.x; d < D_MODEL; d += 256)
        out[d] = te[d] + pe[d];
}

// ---------------- layernorm (single or fused double) ----------------
template <bool DOUBLE>
__global__ void ln_kernel(const float* __restrict__ x,
                          const float* __restrict__ w1, const float* __restrict__ b1,
                          const float* __restrict__ w2, const float* __restrict__ b2,
                          float* __restrict__ y) {
    __shared__ float red[256];
    int row = blockIdx.x;
    int tid = threadIdx.x;
    const float* xr = x + (size_t)row * D_MODEL;
    float v0 = xr[tid], v1 = xr[tid + 256], v2 = xr[tid + 512];

    // pass 1: mean
    red[tid] = v0 + v1 + v2;
    __syncthreads();
    for (int s = 128; s > 0; s >>= 1) { if (tid < s) red[tid] += red[tid + s]; __syncthreads(); }
    float mean = red[0] * (1.0f / D_MODEL);
    __syncthreads();
    float d0 = v0 - mean, d1 = v1 - mean, d2 = v2 - mean;
    red[tid] = d0 * d0 + d1 * d1 + d2 * d2;
    __syncthreads();
    for (int s = 128; s > 0; s >>= 1) { if (tid < s) red[tid] += red[tid + s]; __syncthreads(); }
    float rstd = rsqrtf(red[0] * (1.0f / D_MODEL) + 1e-5f);
    float y0 = d0 * rstd * w1[tid]       + b1[tid];
    float y1 = d1 * rstd * w1[tid + 256] + b1[tid + 256];
    float y2 = d2 * rstd * w1[tid + 512] + b1[tid + 512];

    if (DOUBLE) {
        __syncthreads();
        red[tid] = y0 + y1 + y2;
        __syncthreads();
        for (int s = 128; s > 0; s >>= 1) { if (tid < s) red[tid] += red[tid + s]; __syncthreads(); }
        float mean2 = red[0] * (1.0f / D_MODEL);
        __syncthreads();
        float e0 = y0 - mean2, e1 = y1 - mean2, e2 = y2 - mean2;
        red[tid] = e0 * e0 + e1 * e1 + e2 * e2;
        __syncthreads();
        for (int s = 128; s > 0; s >>= 1) { if (tid < s) red[tid] += red[tid + s]; __syncthreads(); }
        float rstd2 = rsqrtf(red[0] * (1.0f / D_MODEL) + 1e-5f);
        y0 = e0 * rstd2 * w2[tid]       + b2[tid];
        y1 = e1 * rstd2 * w2[tid + 256] + b2[tid + 256];
        y2 = e2 * rstd2 * w2[tid + 512] + b2[tid + 512];
    }
    float* yr = y + (size_t)row * D_MODEL;
    yr[tid] = y0; yr[tid + 256] = y1; yr[tid + 512] = y2;
}

// ---------------- generic SGEMM: C = act(A@B + bias) (+ resid) ----------------
// A: [M,K] row-major. B: row-major [K,N], or HEADED: [N/64][K][64] (qkv weights).
// VECB=false: B row stride not 16B-aligned (e.g. N=50257) -> scalar loads.
// 128x128 tile, BK=8, 256 threads, 8x8 per thread (split 64-offset frags).
template <bool GELU, bool RESID, bool HEADED, bool VECB>
__global__ __launch_bounds__(256)
void gemm_kernel(const float* __restrict__ A, const float* __restrict__ B,
                 const float* __restrict__ bias, const float* __restrict__ resid,
                 float* __restrict__ C, int M, int N, int K) {
    __shared__ float As[8][128];
    __shared__ float Bs[8][128];
    int tid = threadIdx.x;
    int bn = blockIdx.x, bm = blockIdx.y;
    int tx = tid & 15, ty = tid >> 4;

    float acc[8][8];
#pragma unroll
    for (int i = 0; i < 8; i++)
#pragma unroll
        for (int j = 0; j < 8; j++) acc[i][j] = 0.f;

    int arow_l = tid >> 1;                    // 0..127
    int acol0  = (tid & 1) * 4;               // 0 or 4
    int arow   = bm * 128 + arow_l;
    int brow_l = tid >> 5;                    // 0..7
    int bcolg  = (tid & 31) * 4;              // 0..124
    int bcol   = bn * 128 + bcolg;

    for (int k0 = 0; k0 < K; k0 += 8) {
        // load A frag (always in-bounds: M%128==0, K%8==0, K%4==0 alignment)
        float4 av = *(const float4*)(A + (size_t)arow * K + k0 + acol0);
        As[acol0 + 0][arow_l] = av.x;
        As[acol0 + 1][arow_l] = av.y;
        As[acol0 + 2][arow_l] = av.z;
        As[acol0 + 3][arow_l] = av.w;
        // load B frag
        float4 bv;
        if (HEADED) {
            const float* bp = B + (((size_t)(bcol >> 6)) * K + (k0 + brow_l)) * 64 + (bcol & 63);
            bv = *(const float4*)bp;
        } else if (VECB) {
            bv = *(const float4*)(B + (size_t)(k0 + brow_l) * N + bcol);
        } else {
            const float* bp = B + (size_t)(k0 + brow_l) * N;
            bv.x = (bcol + 0 < N) ? bp[bcol + 0] : 0.f;
            bv.y = (bcol + 1 < N) ? bp[bcol + 1] : 0.f;
            bv.z = (bcol + 2 < N) ? bp[bcol + 2] : 0.f;
            bv.w = (bcol + 3 < N) ? bp[bcol + 3] : 0.f;
        }
        *(float4*)&Bs[brow_l][bcolg] = bv;
        __syncthreads();

#pragma unroll
        for (int kk = 0; kk < 8; kk++) {
            float a[8], b[8];
            float4 t;
            t = *(const float4*)&As[kk][ty * 4];        a[0]=t.x; a[1]=t.y; a[2]=t.z; a[3]=t.w;
            t = *(const float4*)&As[kk][ty * 4 + 64];   a[4]=t.x; a[5]=t.y; a[6]=t.z; a[7]=t.w;
            t = *(const float4*)&Bs[kk][tx * 4];        b[0]=t.x; b[1]=t.y; b[2]=t.z; b[3]=t.w;
            t = *(const float4*)&Bs[kk][tx * 4 + 64];   b[4]=t.x; b[5]=t.y; b[6]=t.z; b[7]=t.w;
#pragma unroll
            for (int i = 0; i < 8; i++)
#pragma unroll
                for (int j = 0; j < 8; j++) acc[i][j] += a[i] * b[j];
        }
        __syncthreads();
    }

#pragma unroll
    for (int i = 0; i < 8; i++) {
        int row = bm * 128 + ((i < 4) ? (ty * 4 + i) : (64 + ty * 4 + i - 4));
#pragma unroll
        for (int j = 0; j < 8; j++) {
            int col = bn * 128 + ((j < 4) ? (tx * 4 + j) : (64 + tx * 4 + j - 4));
            if (col < N) {
                float val = acc[i][j] + bias[col];
                if (GELU) val = 0.5f * val * (1.0f + erff(val * 0.70710678118654752f));
                if (RESID) val += resid[(size_t)row * N + col];
                C[(size_t)row * N + col] = val;
            }
        }
    }
}

// ---------------- fused causal attention (flash-style, 64-row query tiles) ----------------
// q/k/v/o are [ROWS, D_MODEL]; per (b,h) the head slab is cols h*64..h*64+63.
#define ATT_SMEM ((4096 + 4160 + 4160) * 4)
__global__ __launch_bounds__(256)
void attn_kernel(const float* __restrict__ q, const float* __restrict__ k,
                 const float* __restrict__ v, float* __restrict__ o) {
    extern __shared__ float sm[];
    float* qs = sm;           // [64][64]
    float* ks = sm + 4096;    // [64][65]  (reused as p)
    float* vs = ks + 4160;    // [64][65]
    int qi = blockIdx.x, hh = blockIdx.y, b = blockIdx.z;
    int tid = threadIdx.x, tx = tid & 15, ty = tid >> 4;
    const size_t base = ((size_t)b * SEQ) * D_MODEL + (size_t)hh * HEAD_DIM;
    const float inv_scale = 0.03608439182435161f;   // 1/sqrt(768)

    for (int idx = tid; idx < 4096; idx += 256) {
        int r = idx >> 6, c = idx & 63;
        qs[idx] = q[base + (size_t)(qi * 64 + r) * D_MODEL + c];
    }

    float m_[4], l_[4], acc[4][4];
#pragma unroll
    for (int r = 0; r < 4; r++) {
        m_[r] = -1e30f; l_[r] = 0.f;
#pragma unroll
        for (int c = 0; c < 4; c++) acc[r][c] = 0.f;
    }

    for (int j = 0; j <= qi; j++) {
        __syncthreads();
        for (int idx = tid; idx < 4096; idx += 256) {
            int r = idx >> 6, c = idx & 63;
            ks[r * 65 + c] = k[base + (size_t)(j * 64 + r) * D_MODEL + c];
            vs[r * 65 + c] = v[base + (size_t)(j * 64 + r) * D_MODEL + c];
        }
        __syncthreads();

        float s[4][4];
#pragma unroll
        for (int r = 0; r < 4; r++)
#pragma unroll
            for (int c = 0; c < 4; c++) s[r][c] = 0.f;

        for (int e = 0; e < 64; e++) {
            float qv[4], kv[4];
#pragma unroll
            for (int r = 0; r < 4; r++) qv[r] = qs[(ty * 4 + r) * 64 + e];
#pragma unroll
            for (int c = 0; c < 4; c++) kv[c] = ks[(tx * 4 + c) * 65 + e];
#pragma unroll
            for (int r = 0; r < 4; r++)
#pragma unroll
                for (int c = 0; c < 4; c++) s[r][c] += qv[r] * kv[c];
        }

#pragma unroll
        for (int r = 0; r < 4; r++)
#pragma unroll
            for (int c = 0; c < 4; c++) {
                s[r][c] *= inv_scale;
                if (j == qi && (tx * 4 + c) > (ty * 4 + r)) s[r][c] = -1e30f;
            }

#pragma unroll
        for (int r = 0; r < 4; r++) {
            float rm = fmaxf(fmaxf(s[r][0], s[r][1]), fmaxf(s[r][2], s[r][3]));
#pragma unroll
            for (int off = 1; off < 16; off <<= 1)
                rm = fmaxf(rm, __shfl_xor_sync(0xffffffffu, rm, off));
            float mnew = fmaxf(m_[r], rm);
            float alpha = __expf(m_[r] - mnew);
            float psum = 0.f;
#pragma unroll
            for (int c = 0; c < 4; c++) { float p = __expf(s[r][c] - mnew); s[r][c] = p; psum += p; }
#pragma unroll
            for (int off = 1; off < 16; off <<= 1)
                psum += __shfl_xor_sync(0xffffffffu, psum, off);
            l_[r] = l_[r] * alpha + psum;
            m_[r] = mnew;
#pragma unroll
            for (int c = 0; c < 4; c++) acc[r][c] *= alpha;
        }

        __syncthreads();   // all ks reads done -> safe to overwrite with p
#pragma unroll
        for (int r = 0; r < 4; r++)
#pragma unroll
            for (int c = 0; c < 4; c++) ks[(ty * 4 + r) * 65 + tx * 4 + c] = s[r][c];
        __syncthreads();

        for (int kk = 0; kk < 64; kk++) {
            float pv[4], vv[4];
#pragma unroll
            for (int r = 0; r < 4; r++) pv[r] = ks[(ty * 4 + r) * 65 + kk];
#pragma unroll
            for (int c = 0; c < 4; c++) vv[c] = vs[kk * 65 + tx * 4 + c];
#pragma unroll
            for (int r = 0; r < 4; r++)
#pragma unroll
                for (int c = 0; c < 4; c++) acc[r][c] += pv[r] * vv[c];
        }
    }

#pragma unroll
    for (int r = 0; r < 4; r++) {
        float invl = 1.0f / l_[r];
#pragma unroll
        for (int c = 0; c < 4; c++)
            o[base + (size_t)(qi * 64 + ty * 4 + r) * D_MODEL + tx * 4 + c] = acc[r][c] * invl;
    }
}

// ---------------- launch ----------------
extern "C" void kernel_launch(void* const* d_in, const int* in_sizes, int n_in,
                              void* d_out, int out_size) {
    const int*   x      = (const int*)  d_in[0];
    const float* wte    = (const float*)d_in[1];
    const float* wpe    = (const float*)d_in[2];
    const float* ln1_w  = (const float*)d_in[3];
    const float* ln1_b  = (const float*)d_in[4];
    const float* Wq     = (const float*)d_in[5];
    const float* bq     = (const float*)d_in[6];
    const float* Wk     = (const float*)d_in[7];
    const float* bk     = (const float*)d_in[8];
    const float* Wv     = (const float*)d_in[9];
    const float* bv     = (const float*)d_in[10];
    const float* Wp     = (const float*)d_in[11];
    const float* bp     = (const float*)d_in[12];
    const float* ln2_w  = (const float*)d_in[13];
    const float* ln2_b  = (const float*)d_in[14];
    const float* lnfc_w = (const float*)d_in[15];
    const float* lnfc_b = (const float*)d_in[16];
    const float* W1     = (const float*)d_in[17];
    const float* b1     = (const float*)d_in[18];
    const float* W2     = (const float*)d_in[19];
    const float* b2     = (const float*)d_in[20];
    const float* lnf_w  = (const float*)d_in[21];
    const float* lnf_b  = (const float*)d_in[22];
    const float* Wh     = (const float*)d_in[23];
    const float* bh     = (const float*)d_in[24];
    float* out = (float*)d_out;

    float *h, *a, *q, *k, *v, *o, *m;
    cudaGetSymbolAddress((void**)&h, g_h);
    cudaGetSymbolAddress((void**)&a, g_a);
    cudaGetSymbolAddress((void**)&q, g_q);
    cudaGetSymbolAddress((void**)&k, g_k);
    cudaGetSymbolAddress((void**)&v, g_v);
    cudaGetSymbolAddress((void**)&o, g_o);
    cudaGetSymbolAddress((void**)&m, g_m);

    cudaFuncSetAttribute(attn_kernel, cudaFuncAttributeMaxDynamicSharedMemorySize, ATT_SMEM);

    embed_kernel<<<ROWS, 256>>>(x, wte, wpe, h);

    dim3 gProj((D_MODEL + 127) / 128, ROWS / 128);   // (6, 32)
    dim3 gFF1((D_FF + 127) / 128, ROWS / 128);       // (24, 32)
    dim3 gHead((VOCAB + 127) / 128, ROWS / 128);     // (393, 32)
    dim3 gAttn(SEQ / 64, N_HEADS, BATCH);            // (16, 12, 4)

    for (int l = 0; l < N_LAYERS; l++) {
        const float* Wq_l = Wq + (size_t)l * N_HEADS * D_MODEL * HEAD_DIM;
        const float* Wk_l = Wk + (size_t)l * N_HEADS * D_MODEL * HEAD_DIM;
        const float* Wv_l = Wv + (size_t)l * N_HEADS * D_MODEL * HEAD_DIM;
        const float* Wp_l = Wp + (size_t)l * D_MODEL * D_MODEL;
        const float* W1_l = W1 + (size_t)l * D_MODEL * D_FF;
        const float* W2_l = W2 + (size_t)l * D_FF * D_MODEL;

        ln_kernel<false><<<ROWS, 256>>>(h, ln1_w + l * D_MODEL, ln1_b + l * D_MODEL,
                                        nullptr, nullptr, a);

        gemm_kernel<false, false, true, true><<<gProj, 256>>>(a, Wq_l, bq + l * D_MODEL, nullptr, q,
                                                              ROWS, D_MODEL, D_MODEL);
        gemm_kernel<false, false, true, true><<<gProj, 256>>>(a, Wk_l, bk + l * D_MODEL, nullptr, k,
                                                              ROWS, D_MODEL, D_MODEL);
        gemm_kernel<false, false, true, true><<<gProj, 256>>>(a, Wv_l, bv + l * D_MODEL, nullptr, v,
                                                              ROWS, D_MODEL, D_MODEL);

        attn_kernel<<<gAttn, 256, ATT_SMEM>>>(q, k, v, o);

        gemm_kernel<false, true, false, true><<<gProj, 256>>>(o, Wp_l, bp + l * D_MODEL, h, h,
                                                              ROWS, D_MODEL, D_MODEL);

        ln_kernel<true><<<ROWS, 256>>>(h, ln2_w + l * D_MODEL, ln2_b + l * D_MODEL,
                                       lnfc_w + l * D_MODEL, lnfc_b + l * D_MODEL, a);

        gemm_kernel<true, false, false, true><<<gFF1, 256>>>(a, W1_l, b1 + l * D_FF, nullptr, m,
                                                             ROWS, D_FF, D_MODEL);
        gemm_kernel<false, true, false, true><<<gProj, 256>>>(m, W2_l, b2 + l * D_MODEL, h, h,
                                                              ROWS, D_MODEL, D_FF);
    }

    ln_kernel<false><<<ROWS, 256>>>(h, lnf_w, lnf_b, nullptr, nullptr, a);
    gemm_kernel<false, false, false, false><<<gHead, 256>>>(a, Wh, bh, nullptr, out,
                                                            ROWS, VOCAB, D_MODEL);
}

// round 3
// speedup vs baseline: 1.3323x; 1.3323x over previous
#include <cuda_runtime.h>
#include <cuda_bf16.h>
#include <math.h>

#define D_MODEL 768
#define N_HEADS 12
#define HEAD_DIM 64
#define N_LAYERS 12
#define SEQ 1024
#define BATCH 4
#define ROWS (BATCH * SEQ)       // 4096
#define D_FF (4 * D_MODEL)       // 3072
#define VOCAB 50257

// ---------------- scratch (device globals; no allocation allowed) ----------------
__device__ float g_h[ROWS * D_MODEL];
__device__ float g_a[ROWS * D_MODEL];
__device__ float g_q[ROWS * D_MODEL];
__device__ float g_k[ROWS * D_MODEL];
__device__ float g_v[ROWS * D_MODEL];
__device__ float g_o[ROWS * D_MODEL];
__device__ float g_m[ROWS * D_FF];

// ---------------- helpers ----------------
__device__ __forceinline__ unsigned f2tf(float x) {
    unsigned r;
    asm("cvt.rna.tf32.f32 %0, %1;" : "=r"(r) : "f"(x));
    return r;
}

__device__ __forceinline__ void mma_tf32(float* c, const unsigned* a, const unsigned* b) {
    asm volatile(
        "mma.sync.aligned.m16n8k8.row.col.f32.tf32.tf32.f32 "
        "{%0,%1,%2,%3}, {%4,%5,%6,%7}, {%8,%9}, {%0,%1,%2,%3};"
        : "+f"(c[0]), "+f"(c[1]), "+f"(c[2]), "+f"(c[3])
        : "r"(a[0]), "r"(a[1]), "r"(a[2]), "r"(a[3]), "r"(b[0]), "r"(b[1]));
}

// ---------------- embedding ----------------
__global__ void embed_kernel(const int* __restrict__ x, const float* __restrict__ wte,
                             const float* __restrict__ wpe, float* __restrict__ h) {
    int row = blockIdx.x;            // 0..4095
    int tok = x[row];
    int s = row & (SEQ - 1);
    const float* te = wte + (size_t)tok * D_MODEL;
    const float* pe = wpe + (size_t)s * D_MODEL;
    float* out = h + (size_t)row * D_MODEL;
    for (int d = threadIdx.x; d < D_MODEL; d += 256)
        out[d] = te[d] + pe[d];
}

// ---------------- layernorm (single or fused double) ----------------
template <bool DOUBLE>
__global__ void ln_kernel(const float* __restrict__ x,
                          const float* __restrict__ w1, const float* __restrict__ b1,
                          const float* __restrict__ w2, const float* __restrict__ b2,
                          float* __restrict__ y) {
    __shared__ float red[256];
    int row = blockIdx.x;
    int tid = threadIdx.x;
    const float* xr = x + (size_t)row * D_MODEL;
    float v0 = xr[tid], v1 = xr[tid + 256], v2 = xr[tid + 512];

    red[tid] = v0 + v1 + v2;
    __syncthreads();
    for (int s = 128; s > 0; s >>= 1) { if (tid < s) red[tid] += red[tid + s]; __syncthreads(); }
    float mean = red[0] * (1.0f / D_MODEL);
    __syncthreads();
    float d0 = v0 - mean, d1 = v1 - mean, d2 = v2 - mean;
    red[tid] = d0 * d0 + d1 * d1 + d2 * d2;
    __syncthreads();
    for (int s = 128; s > 0; s >>= 1) { if (tid < s) red[tid] += red[tid + s]; __syncthreads(); }
    float rstd = rsqrtf(red[0] * (1.0f / D_MODEL) + 1e-5f);
    float y0 = d0 * rstd * w1[tid]       + b1[tid];
    float y1 = d1 * rstd * w1[tid + 256] + b1[tid + 256];
    float y2 = d2 * rstd * w1[tid + 512] + b1[tid + 512];

    if (DOUBLE) {
        __syncthreads();
        red[tid] = y0 + y1 + y2;
        __syncthreads();
        for (int s = 128; s > 0; s >>= 1) { if (tid < s) red[tid] += red[tid + s]; __syncthreads(); }
        float mean2 = red[0] * (1.0f / D_MODEL);
        __syncthreads();
        float e0 = y0 - mean2, e1 = y1 - mean2, e2 = y2 - mean2;
        red[tid] = e0 * e0 + e1 * e1 + e2 * e2;
        __syncthreads();
        for (int s = 128; s > 0; s >>= 1) { if (tid < s) red[tid] += red[tid + s]; __syncthreads(); }
        float rstd2 = rsqrtf(red[0] * (1.0f / D_MODEL) + 1e-5f);
        y0 = e0 * rstd2 * w2[tid]       + b2[tid];
        y1 = e1 * rstd2 * w2[tid + 256] + b2[tid + 256];
        y2 = e2 * rstd2 * w2[tid + 512] + b2[tid + 512];
    }
    float* yr = y + (size_t)row * D_MODEL;
    yr[tid] = y0; yr[tid + 256] = y1; yr[tid + 512] = y2;
}

// ---------------- TF32 tensor-core GEMM: C = act(A@B + bias) (+ resid) ----------------
// A: [M,K] fp32 row-major (M%128==0, K%16==0).
// B: fp32 row-major [K,N], or HEADED: [N/64][K][64] (qkv weights).
// VECB=false: B row stride not 16B-aligned (vocab) -> scalar bounds-checked loads.
// Block tile 128x128x16, 8 warps, warp tile 64x32 via m16n8k8 tf32 mma.
template <bool GELU, bool RESID, bool HEADED, bool VECB>
__global__ __launch_bounds__(256)
void gemm_kernel(const float* __restrict__ A, const float* __restrict__ B,
                 const float* __restrict__ bias, const float* __restrict__ resid,
                 float* __restrict__ C, int M, int N, int K) {
    __shared__ unsigned As[16][136];
    __shared__ unsigned Bs[16][136];
    int tid = threadIdx.x;
    int bn = blockIdx.x, bm = blockIdx.y;
    int lane = tid & 31, warp = tid >> 5;
    int wm = (warp & 1) * 64;       // warp row offset (2 warps along M)
    int wn = (warp >> 1) * 32;      // warp col offset (4 warps along N)
    int lr = lane >> 2;             // 0..7
    int lc = lane & 3;              // 0..3

    float acc[4][4][4];
#pragma unroll
    for (int mi = 0; mi < 4; mi++)
#pragma unroll
        for (int ni = 0; ni < 4; ni++)
#pragma unroll
            for (int r = 0; r < 4; r++) acc[mi][ni][r] = 0.f;

    // staging indices
    int arow_l = tid >> 1;                 // 0..127
    int akc0   = (tid & 1) * 8;            // 0 or 8
    int bkr    = tid >> 4;                 // 0..15
    int bnc    = (tid & 15) * 8;           // 0..120
    int bcol0  = bn * 128 + bnc;

    for (int k0 = 0; k0 < K; k0 += 16) {
        // ---- stage A (transpose to k-major, cvt to tf32) ----
        {
            const float* ap = A + (size_t)(bm * 128 + arow_l) * K + k0 + akc0;
            float4 v0 = *(const float4*)(ap);
            float4 v1 = *(const float4*)(ap + 4);
            As[akc0 + 0][arow_l] = f2tf(v0.x);
            As[akc0 + 1][arow_l] = f2tf(v0.y);
            As[akc0 + 2][arow_l] = f2tf(v0.z);
            As[akc0 + 3][arow_l] = f2tf(v0.w);
            As[akc0 + 4][arow_l] = f2tf(v1.x);
            As[akc0 + 5][arow_l] = f2tf(v1.y);
            As[akc0 + 6][arow_l] = f2tf(v1.z);
            As[akc0 + 7][arow_l] = f2tf(v1.w);
        }
        // ---- stage B (already k-major) ----
        {
            float4 u0, u1;
            if (HEADED) {
                int head = bcol0 >> 6;
                const float* bp = B + ((size_t)head * K + (k0 + bkr)) * 64 + (bcol0 & 63);
                u0 = *(const float4*)(bp);
                u1 = *(const float4*)(bp + 4);
            } else if (VECB) {
                const float* bp = B + (size_t)(k0 + bkr) * N + bcol0;
                u0 = *(const float4*)(bp);
                u1 = *(const float4*)(bp + 4);
            } else {
                const float* bp = B + (size_t)(k0 + bkr) * N;
                u0.x = (bcol0 + 0 < N) ? bp[bcol0 + 0] : 0.f;
                u0.y = (bcol0 + 1 < N) ? bp[bcol0 + 1] : 0.f;
                u0.z = (bcol0 + 2 < N) ? bp[bcol0 + 2] : 0.f;
                u0.w = (bcol0 + 3 < N) ? bp[bcol0 + 3] : 0.f;
                u1.x = (bcol0 + 4 < N) ? bp[bcol0 + 4] : 0.f;
                u1.y = (bcol0 + 5 < N) ? bp[bcol0 + 5] : 0.f;
                u1.z = (bcol0 + 6 < N) ? bp[bcol0 + 6] : 0.f;
                u1.w = (bcol0 + 7 < N) ? bp[bcol0 + 7] : 0.f;
            }
            Bs[bkr][bnc + 0] = f2tf(u0.x);
            Bs[bkr][bnc + 1] = f2tf(u0.y);
            Bs[bkr][bnc + 2] = f2tf(u0.z);
            Bs[bkr][bnc + 3] = f2tf(u0.w);
            Bs[bkr][bnc + 4] = f2tf(u1.x);
            Bs[bkr][bnc + 5] = f2tf(u1.y);
            Bs[bkr][bnc + 6] = f2tf(u1.z);
            Bs[bkr][bnc + 7] = f2tf(u1.w);
        }
        __syncthreads();

#pragma unroll
        for (int ks = 0; ks < 2; ks++) {
            int kb = ks * 8;
            unsigned afr[4][4], bfr[4][2];
#pragma unroll
            for (int mi = 0; mi < 4; mi++) {
                int m0 = wm + mi * 16;
                afr[mi][0] = As[kb + lc][m0 + lr];
                afr[mi][1] = As[kb + lc][m0 + lr + 8];
                afr[mi][2] = As[kb + lc + 4][m0 + lr];
                afr[mi][3] = As[kb + lc + 4][m0 + lr + 8];
            }
#pragma unroll
            for (int ni = 0; ni < 4; ni++) {
                int n0 = wn + ni * 8;
                bfr[ni][0] = Bs[kb + lc][n0 + lr];
                bfr[ni][1] = Bs[kb + lc + 4][n0 + lr];
            }
#pragma unroll
            for (int mi = 0; mi < 4; mi++)
#pragma unroll
                for (int ni = 0; ni < 4; ni++)
                    mma_tf32(acc[mi][ni], afr[mi], bfr[ni]);
        }
        __syncthreads();
    }

    // ---- epilogue ----
#pragma unroll
    for (int mi = 0; mi < 4; mi++) {
        int row0 = bm * 128 + wm + mi * 16 + lr;
#pragma unroll
        for (int ni = 0; ni < 4; ni++) {
            int col = bn * 128 + wn + ni * 8 + lc * 2;
#pragma unroll
            for (int half = 0; half < 2; half++) {
                int row = row0 + half * 8;
#pragma unroll
                for (int cc = 0; cc < 2; cc++) {
                    int c = col + cc;
                    if (VECB || c < N) {
                        float val = acc[mi][ni][half * 2 + cc] + bias[c];
                        if (GELU) val = 0.5f * val * (1.0f + erff(val * 0.70710678118654752f));
                        if (RESID) val += resid[(size_t)row * N + c];
                        C[(size_t)row * N + c] = val;
                    }
                }
            }
        }
    }
}

// ---------------- fused causal attention (flash-style, 64-row query tiles) ----------------
#define ATT_SMEM ((4096 + 4160 + 4160) * 4)
__global__ __launch_bounds__(256)
void attn_kernel(const float* __restrict__ q, const float* __restrict__ k,
                 const float* __restrict__ v, float* __restrict__ o) {
    extern __shared__ float sm[];
    float* qs = sm;           // [64][64]
    float* ks = sm + 4096;    // [64][65]  (reused as p)
    float* vs = ks + 4160;    // [64][65]
    int qi = blockIdx.x, hh = blockIdx.y, b = blockIdx.z;
    int tid = threadIdx.x, tx = tid & 15, ty = tid >> 4;
    const size_t base = ((size_t)b * SEQ) * D_MODEL + (size_t)hh * HEAD_DIM;
    const float inv_scale = 0.03608439182435161f;   // 1/sqrt(768)

    for (int idx = tid; idx < 4096; idx += 256) {
        int r = idx >> 6, c = idx & 63;
        qs[idx] = q[base + (size_t)(qi * 64 + r) * D_MODEL + c];
    }

    float m_[4], l_[4], acc[4][4];
#pragma unroll
    for (int r = 0; r < 4; r++) {
        m_[r] = -1e30f; l_[r] = 0.f;
#pragma unroll
        for (int c = 0; c < 4; c++) acc[r][c] = 0.f;
    }

    for (int j = 0; j <= qi; j++) {
        __syncthreads();
        for (int idx = tid; idx < 4096; idx += 256) {
            int r = idx >> 6, c = idx & 63;
            ks[r * 65 + c] = k[base + (size_t)(j * 64 + r) * D_MODEL + c];
            vs[r * 65 + c] = v[base + (size_t)(j * 64 + r) * D_MODEL + c];
        }
        __syncthreads();

        float s[4][4];
#pragma unroll
        for (int r = 0; r < 4; r++)
#pragma unroll
            for (int c = 0; c < 4; c++) s[r][c] = 0.f;

        for (int e = 0; e < 64; e++) {
            float qv[4], kv[4];
#pragma unroll
            for (int r = 0; r < 4; r++) qv[r] = qs[(ty * 4 + r) * 64 + e];
#pragma unroll
            for (int c = 0; c < 4; c++) kv[c] = ks[(tx * 4 + c) * 65 + e];
#pragma unroll
            for (int r = 0; r < 4; r++)
#pragma unroll
                for (int c = 0; c < 4; c++) s[r][c] += qv[r] * kv[c];
        }

#pragma unroll
        for (int r = 0; r < 4; r++)
#pragma unroll
            for (int c = 0; c < 4; c++) {
                s[r][c] *= inv_scale;
                if (j == qi && (tx * 4 + c) > (ty * 4 + r)) s[r][c] = -1e30f;
            }

#pragma unroll
        for (int r = 0; r < 4; r++) {
            float rm = fmaxf(fmaxf(s[r][0], s[r][1]), fmaxf(s[r][2], s[r][3]));
#pragma unroll
            for (int off = 1; off < 16; off <<= 1)
                rm = fmaxf(rm, __shfl_xor_sync(0xffffffffu, rm, off));
            float mnew = fmaxf(m_[r], rm);
            float alpha = __expf(m_[r] - mnew);
            float psum = 0.f;
#pragma unroll
            for (int c = 0; c < 4; c++) { float p = __expf(s[r][c] - mnew); s[r][c] = p; psum += p; }
#pragma unroll
            for (int off = 1; off < 16; off <<= 1)
                psum += __shfl_xor_sync(0xffffffffu, psum, off);
            l_[r] = l_[r] * alpha + psum;
            m_[r] = mnew;
#pragma unroll
            for (int c = 0; c < 4; c++) acc[r][c] *= alpha;
        }

        __syncthreads();   // all ks reads done -> safe to overwrite with p
#pragma unroll
        for (int r = 0; r < 4; r++)
#pragma unroll
            for (int c = 0; c < 4; c++) ks[(ty * 4 + r) * 65 + tx * 4 + c] = s[r][c];
        __syncthreads();

        for (int kk = 0; kk < 64; kk++) {
            float pv[4], vv[4];
#pragma unroll
            for (int r = 0; r < 4; r++) pv[r] = ks[(ty * 4 + r) * 65 + kk];
#pragma unroll
            for (int c = 0; c < 4; c++) vv[c] = vs[kk * 65 + tx * 4 + c];
#pragma unroll
            for (int r = 0; r < 4; r++)
#pragma unroll
                for (int c = 0; c < 4; c++) acc[r][c] += pv[r] * vv[c];
        }
    }

#pragma unroll
    for (int r = 0; r < 4; r++) {
        float invl = 1.0f / l_[r];
#pragma unroll
        for (int c = 0; c < 4; c++)
            o[base + (size_t)(qi * 64 + ty * 4 + r) * D_MODEL + tx * 4 + c] = acc[r][c] * invl;
    }
}

// ---------------- launch ----------------
extern "C" void kernel_launch(void* const* d_in, const int* in_sizes, int n_in,
                              void* d_out, int out_size) {
    const int*   x      = (const int*)  d_in[0];
    const float* wte    = (const float*)d_in[1];
    const float* wpe    = (const float*)d_in[2];
    const float* ln1_w  = (const float*)d_in[3];
    const float* ln1_b  = (const float*)d_in[4];
    const float* Wq     = (const float*)d_in[5];
    const float* bq     = (const float*)d_in[6];
    const float* Wk     = (const float*)d_in[7];
    const float* bk     = (const float*)d_in[8];
    const float* Wv     = (const float*)d_in[9];
    const float* bv     = (const float*)d_in[10];
    const float* Wp     = (const float*)d_in[11];
    const float* bp     = (const float*)d_in[12];
    const float* ln2_w  = (const float*)d_in[13];
    const float* ln2_b  = (const float*)d_in[14];
    const float* lnfc_w = (const float*)d_in[15];
    const float* lnfc_b = (const float*)d_in[16];
    const float* W1     = (const float*)d_in[17];
    const float* b1     = (const float*)d_in[18];
    const float* W2     = (const float*)d_in[19];
    const float* b2     = (const float*)d_in[20];
    const float* lnf_w  = (const float*)d_in[21];
    const float* lnf_b  = (const float*)d_in[22];
    const float* Wh     = (const float*)d_in[23];
    const float* bh     = (const float*)d_in[24];
    float* out = (float*)d_out;

    float *h, *a, *q, *k, *v, *o, *m;
    cudaGetSymbolAddress((void**)&h, g_h);
    cudaGetSymbolAddress((void**)&a, g_a);
    cudaGetSymbolAddress((void**)&q, g_q);
    cudaGetSymbolAddress((void**)&k, g_k);
    cudaGetSymbolAddress((void**)&v, g_v);
    cudaGetSymbolAddress((void**)&o, g_o);
    cudaGetSymbolAddress((void**)&m, g_m);

    cudaFuncSetAttribute(attn_kernel, cudaFuncAttributeMaxDynamicSharedMemorySize, ATT_SMEM);

    embed_kernel<<<ROWS, 256>>>(x, wte, wpe, h);

    dim3 gProj((D_MODEL + 127) / 128, ROWS / 128);   // (6, 32)
    dim3 gFF1((D_FF + 127) / 128, ROWS / 128);       // (24, 32)
    dim3 gHead((VOCAB + 127) / 128, ROWS / 128);     // (393, 32)
    dim3 gAttn(SEQ / 64, N_HEADS, BATCH);            // (16, 12, 4)

    for (int l = 0; l < N_LAYERS; l++) {
        const float* Wq_l = Wq + (size_t)l * N_HEADS * D_MODEL * HEAD_DIM;
        const float* Wk_l = Wk + (size_t)l * N_HEADS * D_MODEL * HEAD_DIM;
        const float* Wv_l = Wv + (size_t)l * N_HEADS * D_MODEL * HEAD_DIM;
        const float* Wp_l = Wp + (size_t)l * D_MODEL * D_MODEL;
        const float* W1_l = W1 + (size_t)l * D_MODEL * D_FF;
        const float* W2_l = W2 + (size_t)l * D_FF * D_MODEL;

        ln_kernel<false><<<ROWS, 256>>>(h, ln1_w + l * D_MODEL, ln1_b + l * D_MODEL,
                                        nullptr, nullptr, a);

        gemm_kernel<false, false, true, true><<<gProj, 256>>>(a, Wq_l, bq + l * D_MODEL, nullptr, q,
                                                              ROWS, D_MODEL, D_MODEL);
        gemm_kernel<false, false, true, true><<<gProj, 256>>>(a, Wk_l, bk + l * D_MODEL, nullptr, k,
                                                              ROWS, D_MODEL, D_MODEL);
        gemm_kernel<false, false, true, true><<<gProj, 256>>>(a, Wv_l, bv + l * D_MODEL, nullptr, v,
                                                              ROWS, D_MODEL, D_MODEL);

        attn_kernel<<<gAttn, 256, ATT_SMEM>>>(q, k, v, o);

        gemm_kernel<false, true, false, true><<<gProj, 256>>>(o, Wp_l, bp + l * D_MODEL, h, h,
                                                              ROWS, D_MODEL, D_MODEL);

        ln_kernel<true><<<ROWS, 256>>>(h, ln2_w + l * D_MODEL, ln2_b + l * D_MODEL,
                                       lnfc_w + l * D_MODEL, lnfc_b + l * D_MODEL, a);

        gemm_kernel<true, false, false, true><<<gFF1, 256>>>(a, W1_l, b1 + l * D_FF, nullptr, m,
                                                             ROWS, D_FF, D_MODEL);
        gemm_kernel<false, true, false, true><<<gProj, 256>>>(m, W2_l, b2 + l * D_MODEL, h, h,
                                                              ROWS, D_MODEL, D_FF);
    }

    ln_kernel<false><<<ROWS, 256>>>(h, lnf_w, lnf_b, nullptr, nullptr, a);
    gemm_kernel<false, false, false, false><<<gHead, 256>>>(a, Wh, bh, nullptr, out,
                                                            ROWS, VOCAB, D_MODEL);
}

// round 4
// speedup vs baseline: 2.1868x; 1.6414x over previous
#include <cuda_runtime.h>
#include <cuda_bf16.h>
#include <math.h>

#define D_MODEL 768
#define N_HEADS 12
#define HEAD_DIM 64
#define N_LAYERS 12
#define SEQ 1024
#define BATCH 4
#define ROWS (BATCH * SEQ)       // 4096
#define D_FF (4 * D_MODEL)       // 3072
#define VOCAB 50257

// ---------------- scratch (device globals; no allocation allowed) ----------------
__device__ float g_h[ROWS * D_MODEL];
__device__ float g_a[ROWS * D_MODEL];
__device__ float g_q[ROWS * D_MODEL];
__device__ float g_k[ROWS * D_MODEL];
__device__ float g_v[ROWS * D_MODEL];
__device__ float g_o[ROWS * D_MODEL];
__device__ float g_m[ROWS * D_FF];

// ---------------- helpers ----------------
__device__ __forceinline__ unsigned f2tf(float x) {
    unsigned r;
    asm("cvt.rna.tf32.f32 %0, %1;" : "=r"(r) : "f"(x));
    return r;
}

__device__ __forceinline__ void mma_tf32(float* c, const unsigned* a, const unsigned* b) {
    asm volatile(
        "mma.sync.aligned.m16n8k8.row.col.f32.tf32.tf32.f32 "
        "{%0,%1,%2,%3}, {%4,%5,%6,%7}, {%8,%9}, {%0,%1,%2,%3};"
        : "+f"(c[0]), "+f"(c[1]), "+f"(c[2]), "+f"(c[3])
        : "r"(a[0]), "r"(a[1]), "r"(a[2]), "r"(a[3]), "r"(b[0]), "r"(b[1]));
}

// ---------------- embedding ----------------
__global__ void embed_kernel(const int* __restrict__ x, const float* __restrict__ wte,
                             const float* __restrict__ wpe, float* __restrict__ h) {
    int row = blockIdx.x;            // 0..4095
    int tok = x[row];
    int s = row & (SEQ - 1);
    const float* te = wte + (size_t)tok * D_MODEL;
    const float* pe = wpe + (size_t)s * D_MODEL;
    float* out = h + (size_t)row * D_MODEL;
    for (int d = threadIdx.x; d < D_MODEL; d += 256)
        out[d] = te[d] + pe[d];
}

// ---------------- layernorm (single or fused double) ----------------
template <bool DOUBLE>
__global__ void ln_kernel(const float* __restrict__ x,
                          const float* __restrict__ w1, const float* __restrict__ b1,
                          const float* __restrict__ w2, const float* __restrict__ b2,
                          float* __restrict__ y) {
    __shared__ float red[256];
    int row = blockIdx.x;
    int tid = threadIdx.x;
    const float* xr = x + (size_t)row * D_MODEL;
    float v0 = xr[tid], v1 = xr[tid + 256], v2 = xr[tid + 512];

    red[tid] = v0 + v1 + v2;
    __syncthreads();
    for (int s = 128; s > 0; s >>= 1) { if (tid < s) red[tid] += red[tid + s]; __syncthreads(); }
    float mean = red[0] * (1.0f / D_MODEL);
    __syncthreads();
    float d0 = v0 - mean, d1 = v1 - mean, d2 = v2 - mean;
    red[tid] = d0 * d0 + d1 * d1 + d2 * d2;
    __syncthreads();
    for (int s = 128; s > 0; s >>= 1) { if (tid < s) red[tid] += red[tid + s]; __syncthreads(); }
    float rstd = rsqrtf(red[0] * (1.0f / D_MODEL) + 1e-5f);
    float y0 = d0 * rstd * w1[tid]       + b1[tid];
    float y1 = d1 * rstd * w1[tid + 256] + b1[tid + 256];
    float y2 = d2 * rstd * w1[tid + 512] + b1[tid + 512];

    if (DOUBLE) {
        __syncthreads();
        red[tid] = y0 + y1 + y2;
        __syncthreads();
        for (int s = 128; s > 0; s >>= 1) { if (tid < s) red[tid] += red[tid + s]; __syncthreads(); }
        float mean2 = red[0] * (1.0f / D_MODEL);
        __syncthreads();
        float e0 = y0 - mean2, e1 = y1 - mean2, e2 = y2 - mean2;
        red[tid] = e0 * e0 + e1 * e1 + e2 * e2;
        __syncthreads();
        for (int s = 128; s > 0; s >>= 1) { if (tid < s) red[tid] += red[tid + s]; __syncthreads(); }
        float rstd2 = rsqrtf(red[0] * (1.0f / D_MODEL) + 1e-5f);
        y0 = e0 * rstd2 * w2[tid]       + b2[tid];
        y1 = e1 * rstd2 * w2[tid + 256] + b2[tid + 256];
        y2 = e2 * rstd2 * w2[tid + 512] + b2[tid + 512];
    }
    float* yr = y + (size_t)row * D_MODEL;
    yr[tid] = y0; yr[tid + 256] = y1; yr[tid + 512] = y2;
}

// ---------------- TF32 tensor-core GEMM: C = act(A@B + bias) (+ resid) ----------------
// Software-pipelined: register-staged global loads overlap MMAs; double-buffered smem;
// one __syncthreads per k-tile; 2 CTAs/SM.
// A: [M,K] fp32 row-major (M%128==0, K%16==0).
// B: fp32 row-major [K,N], or HEADED: [N/64][K][64] (qkv weights).
// VECB=false: B row stride not 16B-aligned (vocab) -> scalar bounds-checked loads.
template <bool GELU, bool RESID, bool HEADED, bool VECB>
__global__ __launch_bounds__(256, 2)
void gemm_kernel(const float* __restrict__ A, const float* __restrict__ B,
                 const float* __restrict__ bias, const float* __restrict__ resid,
                 float* __restrict__ C, int M, int N, int K) {
    __shared__ unsigned As[2][16][136];
    __shared__ unsigned Bs[2][16][136];
    int tid = threadIdx.x;
    int bn = blockIdx.x, bm = blockIdx.y;
    int lane = tid & 31, warp = tid >> 5;
    int wm = (warp & 1) * 64;       // warp row offset (2 warps along M)
    int wn = (warp >> 1) * 32;      // warp col offset (4 warps along N)
    int lr = lane >> 2;             // 0..7
    int lc = lane & 3;              // 0..3

    float acc[4][4][4];
#pragma unroll
    for (int mi = 0; mi < 4; mi++)
#pragma unroll
        for (int ni = 0; ni < 4; ni++)
#pragma unroll
            for (int r = 0; r < 4; r++) acc[mi][ni][r] = 0.f;

    // staging indices
    int arow_l = tid >> 1;                 // 0..127
    int akc0   = (tid & 1) * 8;            // 0 or 8
    int bkr    = tid >> 4;                 // 0..15
    int bnc    = (tid & 15) * 8;           // 0..120
    int bcol0  = bn * 128 + bnc;

    const float* aptr = A + (size_t)(bm * 128 + arow_l) * K + akc0;
    const float* bptr;
    if (HEADED) {
        int head = bcol0 >> 6;
        bptr = B + ((size_t)head * K + bkr) * 64 + (bcol0 & 63);
    } else {
        bptr = B + (size_t)bkr * N + bcol0;
    }

    float ar[8], br[8];

    // ---- prefetch helpers ----
    auto load_tile = [&](int k0) {
        {
            const float* ap = aptr + k0;
            float4 v0 = *(const float4*)(ap);
            float4 v1 = *(const float4*)(ap + 4);
            ar[0]=v0.x; ar[1]=v0.y; ar[2]=v0.z; ar[3]=v0.w;
            ar[4]=v1.x; ar[5]=v1.y; ar[6]=v1.z; ar[7]=v1.w;
        }
        if (HEADED) {
            const float* bp = bptr + (size_t)k0 * 64;
            float4 u0 = *(const float4*)(bp);
            float4 u1 = *(const float4*)(bp + 4);
            br[0]=u0.x; br[1]=u0.y; br[2]=u0.z; br[3]=u0.w;
            br[4]=u1.x; br[5]=u1.y; br[6]=u1.z; br[7]=u1.w;
        } else if (VECB) {
            const float* bp = bptr + (size_t)k0 * N;
            float4 u0 = *(const float4*)(bp);
            float4 u1 = *(const float4*)(bp + 4);
            br[0]=u0.x; br[1]=u0.y; br[2]=u0.z; br[3]=u0.w;
            br[4]=u1.x; br[5]=u1.y; br[6]=u1.z; br[7]=u1.w;
        } else {
            const float* bp = bptr + (size_t)k0 * N;
#pragma unroll
            for (int j = 0; j < 8; j++)
                br[j] = (bcol0 + j < N) ? bp[j] : 0.f;
        }
    };
    auto store_tile = [&](int buf) {
#pragma unroll
        for (int j = 0; j < 8; j++)
            As[buf][akc0 + j][arow_l] = f2tf(ar[j]);
        uint4 p0, p1;
        p0.x = f2tf(br[0]); p0.y = f2tf(br[1]); p0.z = f2tf(br[2]); p0.w = f2tf(br[3]);
        p1.x = f2tf(br[4]); p1.y = f2tf(br[5]); p1.z = f2tf(br[6]); p1.w = f2tf(br[7]);
        *(uint4*)&Bs[buf][bkr][bnc]     = p0;
        *(uint4*)&Bs[buf][bkr][bnc + 4] = p1;
    };

    load_tile(0);
    store_tile(0);
    __syncthreads();

    int cur = 0;
    for (int k0 = 0; k0 < K; k0 += 16) {
        bool has_next = (k0 + 16) < K;
        if (has_next) load_tile(k0 + 16);   // LDGs in flight during MMAs

#pragma unroll
        for (int ks = 0; ks < 2; ks++) {
            int kb = ks * 8;
            unsigned afr[4][4], bfr[4][2];
#pragma unroll
            for (int mi = 0; mi < 4; mi++) {
                int m0 = wm + mi * 16;
                afr[mi][0] = As[cur][kb + lc][m0 + lr];
                afr[mi][1] = As[cur][kb + lc][m0 + lr + 8];
                afr[mi][2] = As[cur][kb + lc + 4][m0 + lr];
                afr[mi][3] = As[cur][kb + lc + 4][m0 + lr + 8];
            }
#pragma unroll
            for (int ni = 0; ni < 4; ni++) {
                int n0 = wn + ni * 8;
                bfr[ni][0] = Bs[cur][kb + lc][n0 + lr];
                bfr[ni][1] = Bs[cur][kb + lc + 4][n0 + lr];
            }
#pragma unroll
            for (int mi = 0; mi < 4; mi++)
#pragma unroll
                for (int ni = 0; ni < 4; ni++)
                    mma_tf32(acc[mi][ni], afr[mi], bfr[ni]);
        }

        if (has_next) store_tile(cur ^ 1);
        __syncthreads();
        cur ^= 1;
    }

    // ---- epilogue ----
#pragma unroll
    for (int mi = 0; mi < 4; mi++) {
        int row0 = bm * 128 + wm + mi * 16 + lr;
#pragma unroll
        for (int ni = 0; ni < 4; ni++) {
            int col = bn * 128 + wn + ni * 8 + lc * 2;
#pragma unroll
            for (int half = 0; half < 2; half++) {
                int row = row0 + half * 8;
#pragma unroll
                for (int cc = 0; cc < 2; cc++) {
                    int c = col + cc;
                    if (VECB || c < N) {
                        float val = acc[mi][ni][half * 2 + cc] + bias[c];
                        if (GELU) val = 0.5f * val * (1.0f + erff(val * 0.70710678118654752f));
                        if (RESID) val += resid[(size_t)row * N + c];
                        C[(size_t)row * N + c] = val;
                    }
                }
            }
        }
    }
}

// ---------------- fused causal attention (flash-style, 64-row query tiles) ----------------
#define ATT_SMEM ((4096 + 4160 + 4160) * 4)
__global__ __launch_bounds__(256)
void attn_kernel(const float* __restrict__ q, const float* __restrict__ k,
                 const float* __restrict__ v, float* __restrict__ o) {
    extern __shared__ float sm[];
    float* qs = sm;           // [64][64]
    float* ks = sm + 4096;    // [64][65]  (reused as p)
    float* vs = ks + 4160;    // [64][65]
    int qi = blockIdx.x, hh = blockIdx.y, b = blockIdx.z;
    int tid = threadIdx.x, tx = tid & 15, ty = tid >> 4;
    const size_t base = ((size_t)b * SEQ) * D_MODEL + (size_t)hh * HEAD_DIM;
    const float inv_scale = 0.03608439182435161f;   // 1/sqrt(768)

    for (int idx = tid; idx < 4096; idx += 256) {
        int r = idx >> 6, c = idx & 63;
        qs[idx] = q[base + (size_t)(qi * 64 + r) * D_MODEL + c];
    }

    float m_[4], l_[4], acc[4][4];
#pragma unroll
    for (int r = 0; r < 4; r++) {
        m_[r] = -1e30f; l_[r] = 0.f;
#pragma unroll
        for (int c = 0; c < 4; c++) acc[r][c] = 0.f;
    }

    for (int j = 0; j <= qi; j++) {
        __syncthreads();
        for (int idx = tid; idx < 4096; idx += 256) {
            int r = idx >> 6, c = idx & 63;
            ks[r * 65 + c] = k[base + (size_t)(j * 64 + r) * D_MODEL + c];
            vs[r * 65 + c] = v[base + (size_t)(j * 64 + r) * D_MODEL + c];
        }
        __syncthreads();

        float s[4][4];
#pragma unroll
        for (int r = 0; r < 4; r++)
#pragma unroll
            for (int c = 0; c < 4; c++) s[r][c] = 0.f;

        for (int e = 0; e < 64; e++) {
            float qv[4], kv[4];
#pragma unroll
            for (int r = 0; r < 4; r++) qv[r] = qs[(ty * 4 + r) * 64 + e];
#pragma unroll
            for (int c = 0; c < 4; c++) kv[c] = ks[(tx * 4 + c) * 65 + e];
#pragma unroll
            for (int r = 0; r < 4; r++)
#pragma unroll
                for (int c = 0; c < 4; c++) s[r][c] += qv[r] * kv[c];
        }

#pragma unroll
        for (int r = 0; r < 4; r++)
#pragma unroll
            for (int c = 0; c < 4; c++) {
                s[r][c] *= inv_scale;
                if (j == qi && (tx * 4 + c) > (ty * 4 + r)) s[r][c] = -1e30f;
            }

#pragma unroll
        for (int r = 0; r < 4; r++) {
            float rm = fmaxf(fmaxf(s[r][0], s[r][1]), fmaxf(s[r][2], s[r][3]));
#pragma unroll
            for (int off = 1; off < 16; off <<= 1)
                rm = fmaxf(rm, __shfl_xor_sync(0xffffffffu, rm, off));
            float mnew = fmaxf(m_[r], rm);
            float alpha = __expf(m_[r] - mnew);
            float psum = 0.f;
#pragma unroll
            for (int c = 0; c < 4; c++) { float p = __expf(s[r][c] - mnew); s[r][c] = p; psum += p; }
#pragma unroll
            for (int off = 1; off < 16; off <<= 1)
                psum += __shfl_xor_sync(0xffffffffu, psum, off);
            l_[r] = l_[r] * alpha + psum;
            m_[r] = mnew;
#pragma unroll
            for (int c = 0; c < 4; c++) acc[r][c] *= alpha;
        }

        __syncthreads();   // all ks reads done -> safe to overwrite with p
#pragma unroll
        for (int r = 0; r < 4; r++)
#pragma unroll
            for (int c = 0; c < 4; c++) ks[(ty * 4 + r) * 65 + tx * 4 + c] = s[r][c];
        __syncthreads();

        for (int kk = 0; kk < 64; kk++) {
            float pv[4], vv[4];
#pragma unroll
            for (int r = 0; r < 4; r++) pv[r] = ks[(ty * 4 + r) * 65 + kk];
#pragma unroll
            for (int c = 0; c < 4; c++) vv[c] = vs[kk * 65 + tx * 4 + c];
#pragma unroll
            for (int r = 0; r < 4; r++)
#pragma unroll
                for (int c = 0; c < 4; c++) acc[r][c] += pv[r] * vv[c];
        }
    }

#pragma unroll
    for (int r = 0; r < 4; r++) {
        float invl = 1.0f / l_[r];
#pragma unroll
        for (int c = 0; c < 4; c++)
            o[base + (size_t)(qi * 64 + ty * 4 + r) * D_MODEL + tx * 4 + c] = acc[r][c] * invl;
    }
}

// ---------------- launch ----------------
extern "C" void kernel_launch(void* const* d_in, const int* in_sizes, int n_in,
                              void* d_out, int out_size) {
    const int*   x      = (const int*)  d_in[0];
    const float* wte    = (const float*)d_in[1];
    const float* wpe    = (const float*)d_in[2];
    const float* ln1_w  = (const float*)d_in[3];
    const float* ln1_b  = (const float*)d_in[4];
    const float* Wq     = (const float*)d_in[5];
    const float* bq     = (const float*)d_in[6];
    const float* Wk     = (const float*)d_in[7];
    const float* bk     = (const float*)d_in[8];
    const float* Wv     = (const float*)d_in[9];
    const float* bv     = (const float*)d_in[10];
    const float* Wp     = (const float*)d_in[11];
    const float* bp     = (const float*)d_in[12];
    const float* ln2_w  = (const float*)d_in[13];
    const float* ln2_b  = (const float*)d_in[14];
    const float* lnfc_w = (const float*)d_in[15];
    const float* lnfc_b = (const float*)d_in[16];
    const float* W1     = (const float*)d_in[17];
    const float* b1     = (const float*)d_in[18];
    const float* W2     = (const float*)d_in[19];
    const float* b2     = (const float*)d_in[20];
    const float* lnf_w  = (const float*)d_in[21];
    const float* lnf_b  = (const float*)d_in[22];
    const float* Wh     = (const float*)d_in[23];
    const float* bh     = (const float*)d_in[24];
    float* out = (float*)d_out;

    float *h, *a, *q, *k, *v, *o, *m;
    cudaGetSymbolAddress((void**)&h, g_h);
    cudaGetSymbolAddress((void**)&a, g_a);
    cudaGetSymbolAddress((void**)&q, g_q);
    cudaGetSymbolAddress((void**)&k, g_k);
    cudaGetSymbolAddress((void**)&v, g_v);
    cudaGetSymbolAddress((void**)&o, g_o);
    cudaGetSymbolAddress((void**)&m, g_m);

    cudaFuncSetAttribute(attn_kernel, cudaFuncAttributeMaxDynamicSharedMemorySize, ATT_SMEM);

    embed_kernel<<<ROWS, 256>>>(x, wte, wpe, h);

    dim3 gProj((D_MODEL + 127) / 128, ROWS / 128);   // (6, 32)
    dim3 gFF1((D_FF + 127) / 128, ROWS / 128);       // (24, 32)
    dim3 gHead((VOCAB + 127) / 128, ROWS / 128);     // (393, 32)
    dim3 gAttn(SEQ / 64, N_HEADS, BATCH);            // (16, 12, 4)

    for (int l = 0; l < N_LAYERS; l++) {
        const float* Wq_l = Wq + (size_t)l * N_HEADS * D_MODEL * HEAD_DIM;
        const float* Wk_l = Wk + (size_t)l * N_HEADS * D_MODEL * HEAD_DIM;
        const float* Wv_l = Wv + (size_t)l * N_HEADS * D_MODEL * HEAD_DIM;
        const float* Wp_l = Wp + (size_t)l * D_MODEL * D_MODEL;
        const float* W1_l = W1 + (size_t)l * D_MODEL * D_FF;
        const float* W2_l = W2 + (size_t)l * D_FF * D_MODEL;

        ln_kernel<false><<<ROWS, 256>>>(h, ln1_w + l * D_MODEL, ln1_b + l * D_MODEL,
                                        nullptr, nullptr, a);

        gemm_kernel<false, false, true, true><<<gProj, 256>>>(a, Wq_l, bq + l * D_MODEL, nullptr, q,
                                                              ROWS, D_MODEL, D_MODEL);
        gemm_kernel<false, false, true, true><<<gProj, 256>>>(a, Wk_l, bk + l * D_MODEL, nullptr, k,
                                                              ROWS, D_MODEL, D_MODEL);
        gemm_kernel<false, false, true, true><<<gProj, 256>>>(a, Wv_l, bv + l * D_MODEL, nullptr, v,
                                                              ROWS, D_MODEL, D_MODEL);

        attn_kernel<<<gAttn, 256, ATT_SMEM>>>(q, k, v, o);

        gemm_kernel<false, true, false, true><<<gProj, 256>>>(o, Wp_l, bp + l * D_MODEL, h, h,
                                                              ROWS, D_MODEL, D_MODEL);

        ln_kernel<true><<<ROWS, 256>>>(h, ln2_w + l * D_MODEL, ln2_b + l * D_MODEL,
                                       lnfc_w + l * D_MODEL, lnfc_b + l * D_MODEL, a);

        gemm_kernel<true, false, false, true><<<gFF1, 256>>>(a, W1_l, b1 + l * D_FF, nullptr, m,
                                                             ROWS, D_FF, D_MODEL);
        gemm_kernel<false, true, false, true><<<gProj, 256>>>(m, W2_l, b2 + l * D_MODEL, h, h,
                                                              ROWS, D_MODEL, D_FF);
    }

    ln_kernel<false><<<ROWS, 256>>>(h, lnf_w, lnf_b, nullptr, nullptr, a);
    gemm_kernel<false, false, false, false><<<gHead, 256>>>(a, Wh, bh, nullptr, out,
                                                            ROWS, VOCAB, D_MODEL);
}

// round 5
// speedup vs baseline: 2.3935x; 1.0945x over previous
#include <cuda_runtime.h>
#include <cuda_bf16.h>
#include <math.h>

#define D_MODEL 768
#define N_HEADS 12
#define HEAD_DIM 64
#define N_LAYERS 12
#define SEQ 1024
#define BATCH 4
#define ROWS (BATCH * SEQ)       // 4096
#define D_FF (4 * D_MODEL)       // 3072
#define VOCAB 50257

// ---------------- scratch (device globals; no allocation allowed) ----------------
__device__ float g_h[ROWS * D_MODEL];
__device__ float g_a[ROWS * D_MODEL];
__device__ float g_q[ROWS * D_MODEL];
__device__ float g_k[ROWS * D_MODEL];
__device__ float g_v[ROWS * D_MODEL];
__device__ float g_o[ROWS * D_MODEL];
__device__ float g_m[ROWS * D_FF];

// ---------------- helpers ----------------
__device__ __forceinline__ unsigned f2tf(float x) {
    unsigned r;
    asm("cvt.rna.tf32.f32 %0, %1;" : "=r"(r) : "f"(x));
    return r;
}

__device__ __forceinline__ void mma_tf32(float* c, const unsigned* a, const unsigned* b) {
    asm volatile(
        "mma.sync.aligned.m16n8k8.row.col.f32.tf32.tf32.f32 "
        "{%0,%1,%2,%3}, {%4,%5,%6,%7}, {%8,%9}, {%0,%1,%2,%3};"
        : "+f"(c[0]), "+f"(c[1]), "+f"(c[2]), "+f"(c[3])
        : "r"(a[0]), "r"(a[1]), "r"(a[2]), "r"(a[3]), "r"(b[0]), "r"(b[1]));
}

// ---------------- embedding ----------------
__global__ void embed_kernel(const int* __restrict__ x, const float* __restrict__ wte,
                             const float* __restrict__ wpe, float* __restrict__ h) {
    int row = blockIdx.x;            // 0..4095
    int tok = x[row];
    int s = row & (SEQ - 1);
    const float* te = wte + (size_t)tok * D_MODEL;
    const float* pe = wpe + (size_t)s * D_MODEL;
    float* out = h + (size_t)row * D_MODEL;
    for (int d = threadIdx.x; d < D_MODEL; d += 256)
        out[d] = te[d] + pe[d];
}

// ---------------- layernorm (single or fused double) ----------------
template <bool DOUBLE>
__global__ void ln_kernel(const float* __restrict__ x,
                          const float* __restrict__ w1, const float* __restrict__ b1,
                          const float* __restrict__ w2, const float* __restrict__ b2,
                          float* __restrict__ y) {
    __shared__ float red[256];
    int row = blockIdx.x;
    int tid = threadIdx.x;
    const float* xr = x + (size_t)row * D_MODEL;
    float v0 = xr[tid], v1 = xr[tid + 256], v2 = xr[tid + 512];

    red[tid] = v0 + v1 + v2;
    __syncthreads();
    for (int s = 128; s > 0; s >>= 1) { if (tid < s) red[tid] += red[tid + s]; __syncthreads(); }
    float mean = red[0] * (1.0f / D_MODEL);
    __syncthreads();
    float d0 = v0 - mean, d1 = v1 - mean, d2 = v2 - mean;
    red[tid] = d0 * d0 + d1 * d1 + d2 * d2;
    __syncthreads();
    for (int s = 128; s > 0; s >>= 1) { if (tid < s) red[tid] += red[tid + s]; __syncthreads(); }
    float rstd = rsqrtf(red[0] * (1.0f / D_MODEL) + 1e-5f);
    float y0 = d0 * rstd * w1[tid]       + b1[tid];
    float y1 = d1 * rstd * w1[tid + 256] + b1[tid + 256];
    float y2 = d2 * rstd * w1[tid + 512] + b1[tid + 512];

    if (DOUBLE) {
        __syncthreads();
        red[tid] = y0 + y1 + y2;
        __syncthreads();
        for (int s = 128; s > 0; s >>= 1) { if (tid < s) red[tid] += red[tid + s]; __syncthreads(); }
        float mean2 = red[0] * (1.0f / D_MODEL);
        __syncthreads();
        float e0 = y0 - mean2, e1 = y1 - mean2, e2 = y2 - mean2;
        red[tid] = e0 * e0 + e1 * e1 + e2 * e2;
        __syncthreads();
        for (int s = 128; s > 0; s >>= 1) { if (tid < s) red[tid] += red[tid + s]; __syncthreads(); }
        float rstd2 = rsqrtf(red[0] * (1.0f / D_MODEL) + 1e-5f);
        y0 = e0 * rstd2 * w2[tid]       + b2[tid];
        y1 = e1 * rstd2 * w2[tid + 256] + b2[tid + 256];
        y2 = e2 * rstd2 * w2[tid + 512] + b2[tid + 512];
    }
    float* yr = y + (size_t)row * D_MODEL;
    yr[tid] = y0; yr[tid + 256] = y1; yr[tid + 512] = y2;
}

// ---------------- TF32 tensor-core GEMM body ----------------
// Software-pipelined, double-buffered. A staged in MMA-fragment order with XOR
// swizzle so consumers read one LDS.128 per 16x16 A tile. B in k-major smem.
// A: [M,K] fp32 row-major (M%128==0, K%16==0).
// B: fp32 row-major [K,N], or HEADED: [N/64][K][64] (qkv weights).
// VECB=false: B row stride not 16B-aligned (vocab) -> scalar bounds-checked loads.
template <bool GELU, bool RESID, bool HEADED, bool VECB>
__device__ __forceinline__
void gemm_body(const float* __restrict__ A, const float* __restrict__ B,
               const float* __restrict__ bias, const float* __restrict__ resid,
               float* __restrict__ C, int M, int N, int K, int bn, int bm) {
    // A fragments: [buf][mi(8)][ks(2)][lane(32)][slot(4)]
    __shared__ unsigned Asf[2][8][2][32][4];
    __shared__ unsigned Bs[2][16][136];
    int tid = threadIdx.x;
    int lane = tid & 31, warp = tid >> 5;
    int wm = (warp & 1) * 64;       // warp row offset (2 warps along M)
    int wn = (warp >> 1) * 32;      // warp col offset (4 warps along N)
    int lr = lane >> 2;             // 0..7
    int lc = lane & 3;              // 0..3
    int lane_s = lr * 4 + (lc ^ ((lr >> 1) & 3));   // consumer swizzled lane

    float acc[4][4][4];
#pragma unroll
    for (int mi = 0; mi < 4; mi++)
#pragma unroll
        for (int ni = 0; ni < 4; ni++)
#pragma unroll
            for (int r = 0; r < 4; r++) acc[mi][ni][r] = 0.f;

    // ---- staging indices ----
    int arow_l = tid >> 1;                 // 0..127
    int aks    = tid & 1;                  // which ks half this thread stages
    int ami    = arow_l >> 4;              // A mtile
    int alr    = arow_l & 7;
    int ahi    = (arow_l >> 3) & 1;
    int asw    = (alr >> 1) & 3;           // staging swizzle
    int bkr    = tid >> 4;                 // 0..15
    int bnc    = (tid & 15) * 8;           // 0..120
    int bcol0  = bn * 128 + bnc;

    const float* aptr = A + (size_t)(bm * 128 + arow_l) * K + aks * 8;
    const float* bptr;
    if (HEADED) {
        int head = bcol0 >> 6;
        bptr = B + ((size_t)head * K + bkr) * 64 + (bcol0 & 63);
    } else {
        bptr = B + (size_t)bkr * N + bcol0;
    }

    float ar[8], br[8];

    auto load_tile = [&](int k0) {
        {
            const float* ap = aptr + k0;
            float4 v0 = *(const float4*)(ap);
            float4 v1 = *(const float4*)(ap + 4);
            ar[0]=v0.x; ar[1]=v0.y; ar[2]=v0.z; ar[3]=v0.w;
            ar[4]=v1.x; ar[5]=v1.y; ar[6]=v1.z; ar[7]=v1.w;
        }
        if (HEADED) {
            const float* bp = bptr + (size_t)k0 * 64;
            float4 u0 = *(const float4*)(bp);
            float4 u1 = *(const float4*)(bp + 4);
            br[0]=u0.x; br[1]=u0.y; br[2]=u0.z; br[3]=u0.w;
            br[4]=u1.x; br[5]=u1.y; br[6]=u1.z; br[7]=u1.w;
        } else if (VECB) {
            const float* bp = bptr + (size_t)k0 * N;
            float4 u0 = *(const float4*)(bp);
            float4 u1 = *(const float4*)(bp + 4);
            br[0]=u0.x; br[1]=u0.y; br[2]=u0.z; br[3]=u0.w;
            br[4]=u1.x; br[5]=u1.y; br[6]=u1.z; br[7]=u1.w;
        } else {
            const float* bp = bptr + (size_t)k0 * N;
#pragma unroll
            for (int j = 0; j < 8; j++)
                br[j] = (bcol0 + j < N) ? bp[j] : 0.f;
        }
    };
    auto store_tile = [&](int buf) {
        unsigned* abase = &Asf[buf][ami][aks][0][0];
#pragma unroll
        for (int j = 0; j < 8; j++) {
            int ls   = alr * 4 + ((j & 3) ^ asw);
            int slot = ahi + 2 * (j >> 2);
            abase[ls * 4 + slot] = f2tf(ar[j]);
        }
        uint4 p0, p1;
        p0.x = f2tf(br[0]); p0.y = f2tf(br[1]); p0.z = f2tf(br[2]); p0.w = f2tf(br[3]);
        p1.x = f2tf(br[4]); p1.y = f2tf(br[5]); p1.z = f2tf(br[6]); p1.w = f2tf(br[7]);
        *(uint4*)&Bs[buf][bkr][bnc]     = p0;
        *(uint4*)&Bs[buf][bkr][bnc + 4] = p1;
    };

    load_tile(0);
    store_tile(0);
    __syncthreads();

    int cur = 0;
    for (int k0 = 0; k0 < K; k0 += 16) {
        bool has_next = (k0 + 16) < K;
        if (has_next) load_tile(k0 + 16);   // LDGs in flight during MMAs

#pragma unroll
        for (int ks = 0; ks < 2; ks++) {
            int kb = ks * 8;
            unsigned afr[4][4], bfr[4][2];
#pragma unroll
            for (int mi = 0; mi < 4; mi++) {
                int mig = (warp & 1) * 4 + mi;
                uint4 fa = *(const uint4*)&Asf[cur][mig][ks][lane_s][0];
                afr[mi][0] = fa.x; afr[mi][1] = fa.y;
                afr[mi][2] = fa.z; afr[mi][3] = fa.w;
            }
#pragma unroll
            for (int ni = 0; ni < 4; ni++) {
                int n0 = wn + ni * 8;
                bfr[ni][0] = Bs[cur][kb + lc][n0 + lr];
                bfr[ni][1] = Bs[cur][kb + lc + 4][n0 + lr];
            }
#pragma unroll
            for (int mi = 0; mi < 4; mi++)
#pragma unroll
                for (int ni = 0; ni < 4; ni++)
                    mma_tf32(acc[mi][ni], afr[mi], bfr[ni]);
        }

        if (has_next) store_tile(cur ^ 1);
        __syncthreads();
        cur ^= 1;
    }

    // ---- epilogue ----
#pragma unroll
    for (int mi = 0; mi < 4; mi++) {
        int row0 = bm * 128 + wm + mi * 16 + lr;
#pragma unroll
        for (int ni = 0; ni < 4; ni++) {
            int col = bn * 128 + wn + ni * 8 + lc * 2;
#pragma unroll
            for (int half = 0; half < 2; half++) {
                int row = row0 + half * 8;
#pragma unroll
                for (int cc = 0; cc < 2; cc++) {
                    int c = col + cc;
                    if (VECB || c < N) {
                        float val = acc[mi][ni][half * 2 + cc] + bias[c];
                        if (GELU) val = 0.5f * val * (1.0f + erff(val * 0.70710678118654752f));
                        if (RESID) val += resid[(size_t)row * N + c];
                        C[(size_t)row * N + c] = val;
                    }
                }
            }
        }
    }
}

template <bool GELU, bool RESID, bool HEADED, bool VECB>
__global__ __launch_bounds__(256, 2)
void gemm_kernel(const float* __restrict__ A, const float* __restrict__ B,
                 const float* __restrict__ bias, const float* __restrict__ resid,
                 float* __restrict__ C, int M, int N, int K) {
    gemm_body<GELU, RESID, HEADED, VECB>(A, B, bias, resid, C, M, N, K,
                                         blockIdx.x, blockIdx.y);
}

// Fused Q/K/V projection: blockIdx.z selects which of the three GEMMs.
__global__ __launch_bounds__(256, 2)
void qkv_kernel(const float* __restrict__ A,
                const float* __restrict__ Wq, const float* __restrict__ Wk,
                const float* __restrict__ Wv,
                const float* __restrict__ bq, const float* __restrict__ bk,
                const float* __restrict__ bv,
                float* __restrict__ q, float* __restrict__ k, float* __restrict__ v) {
    const float* B    = (blockIdx.z == 0) ? Wq : (blockIdx.z == 1) ? Wk : Wv;
    const float* bias = (blockIdx.z == 0) ? bq : (blockIdx.z == 1) ? bk : bv;
    float*       C    = (blockIdx.z == 0) ? q  : (blockIdx.z == 1) ? k  : v;
    gemm_body<false, false, true, true>(A, B, bias, nullptr, C,
                                        ROWS, D_MODEL, D_MODEL, blockIdx.x, blockIdx.y);
}

// ---------------- fused causal attention (flash-style, 64-row query tiles) ----------------
#define ATT_SMEM ((4096 + 4160 + 4160) * 4)
__global__ __launch_bounds__(256)
void attn_kernel(const float* __restrict__ q, const float* __restrict__ k,
                 const float* __restrict__ v, float* __restrict__ o) {
    extern __shared__ float sm[];
    float* qs = sm;           // [64][64]
    float* ks = sm + 4096;    // [64][65]  (reused as p)
    float* vs = ks + 4160;    // [64][65]
    int qi = blockIdx.x, hh = blockIdx.y, b = blockIdx.z;
    int tid = threadIdx.x, tx = tid & 15, ty = tid >> 4;
    const size_t base = ((size_t)b * SEQ) * D_MODEL + (size_t)hh * HEAD_DIM;
    const float inv_scale = 0.03608439182435161f;   // 1/sqrt(768)

    for (int idx = tid; idx < 4096; idx += 256) {
        int r = idx >> 6, c = idx & 63;
        qs[idx] = q[base + (size_t)(qi * 64 + r) * D_MODEL + c];
    }

    float m_[4], l_[4], acc[4][4];
#pragma unroll
    for (int r = 0; r < 4; r++) {
        m_[r] = -1e30f; l_[r] = 0.f;
#pragma unroll
        for (int c = 0; c < 4; c++) acc[r][c] = 0.f;
    }

    for (int j = 0; j <= qi; j++) {
        __syncthreads();
        for (int idx = tid; idx < 4096; idx += 256) {
            int r = idx >> 6, c = idx & 63;
            ks[r * 65 + c] = k[base + (size_t)(j * 64 + r) * D_MODEL + c];
            vs[r * 65 + c] = v[base + (size_t)(j * 64 + r) * D_MODEL + c];
        }
        __syncthreads();

        float s[4][4];
#pragma unroll
        for (int r = 0; r < 4; r++)
#pragma unroll
            for (int c = 0; c < 4; c++) s[r][c] = 0.f;

        for (int e = 0; e < 64; e++) {
            float qv[4], kv[4];
#pragma unroll
            for (int r = 0; r < 4; r++) qv[r] = qs[(ty * 4 + r) * 64 + e];
#pragma unroll
            for (int c = 0; c < 4; c++) kv[c] = ks[(tx * 4 + c) * 65 + e];
#pragma unroll
            for (int r = 0; r < 4; r++)
#pragma unroll
                for (int c = 0; c < 4; c++) s[r][c] += qv[r] * kv[c];
        }

#pragma unroll
        for (int r = 0; r < 4; r++)
#pragma unroll
            for (int c = 0; c < 4; c++) {
                s[r][c] *= inv_scale;
                if (j == qi && (tx * 4 + c) > (ty * 4 + r)) s[r][c] = -1e30f;
            }

#pragma unroll
        for (int r = 0; r < 4; r++) {
            float rm = fmaxf(fmaxf(s[r][0], s[r][1]), fmaxf(s[r][2], s[r][3]));
#pragma unroll
            for (int off = 1; off < 16; off <<= 1)
                rm = fmaxf(rm, __shfl_xor_sync(0xffffffffu, rm, off));
            float mnew = fmaxf(m_[r], rm);
            float alpha = __expf(m_[r] - mnew);
            float psum = 0.f;
#pragma unroll
            for (int c = 0; c < 4; c++) { float p = __expf(s[r][c] - mnew); s[r][c] = p; psum += p; }
#pragma unroll
            for (int off = 1; off < 16; off <<= 1)
                psum += __shfl_xor_sync(0xffffffffu, psum, off);
            l_[r] = l_[r] * alpha + psum;
            m_[r] = mnew;
#pragma unroll
            for (int c = 0; c < 4; c++) acc[r][c] *= alpha;
        }

        __syncthreads();   // all ks reads done -> safe to overwrite with p
#pragma unroll
        for (int r = 0; r < 4; r++)
#pragma unroll
            for (int c = 0; c < 4; c++) ks[(ty * 4 + r) * 65 + tx * 4 + c] = s[r][c];
        __syncthreads();

        for (int kk = 0; kk < 64; kk++) {
            float pv[4], vv[4];
#pragma unroll
            for (int r = 0; r < 4; r++) pv[r] = ks[(ty * 4 + r) * 65 + kk];
#pragma unroll
            for (int c = 0; c < 4; c++) vv[c] = vs[kk * 65 + tx * 4 + c];
#pragma unroll
            for (int r = 0; r < 4; r++)
#pragma unroll
                for (int c = 0; c < 4; c++) acc[r][c] += pv[r] * vv[c];
        }
    }

#pragma unroll
    for (int r = 0; r < 4; r++) {
        float invl = 1.0f / l_[r];
#pragma unroll
        for (int c = 0; c < 4; c++)
            o[base + (size_t)(qi * 64 + ty * 4 + r) * D_MODEL + tx * 4 + c] = acc[r][c] * invl;
    }
}

// ---------------- launch ----------------
extern "C" void kernel_launch(void* const* d_in, const int* in_sizes, int n_in,
                              void* d_out, int out_size) {
    const int*   x      = (const int*)  d_in[0];
    const float* wte    = (const float*)d_in[1];
    const float* wpe    = (const float*)d_in[2];
    const float* ln1_w  = (const float*)d_in[3];
    const float* ln1_b  = (const float*)d_in[4];
    const float* Wq     = (const float*)d_in[5];
    const float* bq     = (const float*)d_in[6];
    const float* Wk     = (const float*)d_in[7];
    const float* bk     = (const float*)d_in[8];
    const float* Wv     = (const float*)d_in[9];
    const float* bv     = (const float*)d_in[10];
    const float* Wp     = (const float*)d_in[11];
    const float* bp     = (const float*)d_in[12];
    const float* ln2_w  = (const float*)d_in[13];
    const float* ln2_b  = (const float*)d_in[14];
    const float* lnfc_w = (const float*)d_in[15];
    const float* lnfc_b = (const float*)d_in[16];
    const float* W1     = (const float*)d_in[17];
    const float* b1     = (const float*)d_in[18];
    const float* W2     = (const float*)d_in[19];
    const float* b2     = (const float*)d_in[20];
    const float* lnf_w  = (const float*)d_in[21];
    const float* lnf_b  = (const float*)d_in[22];
    const float* Wh     = (const float*)d_in[23];
    const float* bh     = (const float*)d_in[24];
    float* out = (float*)d_out;

    float *h, *a, *q, *k, *v, *o, *m;
    cudaGetSymbolAddress((void**)&h, g_h);
    cudaGetSymbolAddress((void**)&a, g_a);
    cudaGetSymbolAddress((void**)&q, g_q);
    cudaGetSymbolAddress((void**)&k, g_k);
    cudaGetSymbolAddress((void**)&v, g_v);
    cudaGetSymbolAddress((void**)&o, g_o);
    cudaGetSymbolAddress((void**)&m, g_m);

    cudaFuncSetAttribute(attn_kernel, cudaFuncAttributeMaxDynamicSharedMemorySize, ATT_SMEM);

    embed_kernel<<<ROWS, 256>>>(x, wte, wpe, h);

    dim3 gQKV((D_MODEL + 127) / 128, ROWS / 128, 3);  // (6, 32, 3)
    dim3 gProj((D_MODEL + 127) / 128, ROWS / 128);    // (6, 32)
    dim3 gFF1((D_FF + 127) / 128, ROWS / 128);        // (24, 32)
    dim3 gHead((VOCAB + 127) / 128, ROWS / 128);      // (393, 32)
    dim3 gAttn(SEQ / 64, N_HEADS, BATCH);             // (16, 12, 4)

    for (int l = 0; l < N_LAYERS; l++) {
        const float* Wq_l = Wq + (size_t)l * N_HEADS * D_MODEL * HEAD_DIM;
        const float* Wk_l = Wk + (size_t)l * N_HEADS * D_MODEL * HEAD_DIM;
        const float* Wv_l = Wv + (size_t)l * N_HEADS * D_MODEL * HEAD_DIM;
        const float* Wp_l = Wp + (size_t)l * D_MODEL * D_MODEL;
        const float* W1_l = W1 + (size_t)l * D_MODEL * D_FF;
        const float* W2_l = W2 + (size_t)l * D_FF * D_MODEL;

        ln_kernel<false><<<ROWS, 256>>>(h, ln1_w + l * D_MODEL, ln1_b + l * D_MODEL,
                                        nullptr, nullptr, a);

        qkv_kernel<<<gQKV, 256>>>(a, Wq_l, Wk_l, Wv_l,
                                  bq + l * D_MODEL, bk + l * D_MODEL, bv + l * D_MODEL,
                                  q, k, v);

        attn_kernel<<<gAttn, 256, ATT_SMEM>>>(q, k, v, o);

        gemm_kernel<false, true, false, true><<<gProj, 256>>>(o, Wp_l, bp + l * D_MODEL, h, h,
                                                              ROWS, D_MODEL, D_MODEL);

        ln_kernel<true><<<ROWS, 256>>>(h, ln2_w + l * D_MODEL, ln2_b + l * D_MODEL,
                                       lnfc_w + l * D_MODEL, lnfc_b + l * D_MODEL, a);

        gemm_kernel<true, false, false, true><<<gFF1, 256>>>(a, W1_l, b1 + l * D_FF, nullptr, m,
                                                             ROWS, D_FF, D_MODEL);
        gemm_kernel<false, true, false, true><<<gProj, 256>>>(m, W2_l, b2 + l * D_MODEL, h, h,
                                                              ROWS, D_MODEL, D_FF);
    }

    ln_kernel<false><<<ROWS, 256>>>(h, lnf_w, lnf_b, nullptr, nullptr, a);
    gemm_kernel<false, false, false, false><<<gHead, 256>>>(a, Wh, bh, nullptr, out,
                                                            ROWS, VOCAB, D_MODEL);
}

// round 6
// speedup vs baseline: 2.5890x; 1.0817x over previous
#include <cuda_runtime.h>
#include <cuda_bf16.h>
#include <math.h>

#define D_MODEL 768
#define N_HEADS 12
#define HEAD_DIM 64
#define N_LAYERS 12
#define SEQ 1024
#define BATCH 4
#define ROWS (BATCH * SEQ)       // 4096
#define D_FF (4 * D_MODEL)       // 3072
#define VOCAB 50257
#define VOCAB_P 50304            // padded to multiple of 128

// ---------------- scratch (device globals; no allocation allowed) ----------------
__device__ float g_h[ROWS * D_MODEL];
__device__ float g_a[ROWS * D_MODEL];
__device__ float g_q[ROWS * D_MODEL];
__device__ float g_k[ROWS * D_MODEL];
__device__ float g_v[ROWS * D_MODEL];
__device__ float g_o[ROWS * D_MODEL];
__device__ float g_m[ROWS * D_FF];
__device__ float g_whp[D_MODEL * VOCAB_P];   // padded LM head weight

// ---------------- helpers ----------------
__device__ __forceinline__ unsigned f2tf(float x) {
    unsigned r;
    asm("cvt.rna.tf32.f32 %0, %1;" : "=r"(r) : "f"(x));
    return r;
}

__device__ __forceinline__ void mma_tf32(float* c, const unsigned* a, const unsigned* b) {
    asm volatile(
        "mma.sync.aligned.m16n8k8.row.col.f32.tf32.tf32.f32 "
        "{%0,%1,%2,%3}, {%4,%5,%6,%7}, {%8,%9}, {%0,%1,%2,%3};"
        : "+f"(c[0]), "+f"(c[1]), "+f"(c[2]), "+f"(c[3])
        : "r"(a[0]), "r"(a[1]), "r"(a[2]), "r"(a[3]), "r"(b[0]), "r"(b[1]));
}

// ---------------- embedding ----------------
__global__ void embed_kernel(const int* __restrict__ x, const float* __restrict__ wte,
                             const float* __restrict__ wpe, float* __restrict__ h) {
    int row = blockIdx.x;            // 0..4095
    int tok = x[row];
    int s = row & (SEQ - 1);
    const float* te = wte + (size_t)tok * D_MODEL;
    const float* pe = wpe + (size_t)s * D_MODEL;
    float* out = h + (size_t)row * D_MODEL;
    for (int d = threadIdx.x; d < D_MODEL; d += 256)
        out[d] = te[d] + pe[d];
}

// ---------------- pad LM head weight ----------------
__global__ void pad_wh_kernel(const float* __restrict__ Wh, float* __restrict__ WhP) {
    int row = blockIdx.y;
    int col = blockIdx.x * 256 + threadIdx.x;
    if (col < VOCAB_P)
        WhP[(size_t)row * VOCAB_P + col] =
            (col < VOCAB) ? Wh[(size_t)row * VOCAB + col] : 0.f;
}

// ---------------- layernorm (single or fused double) ----------------
template <bool DOUBLE>
__global__ void ln_kernel(const float* __restrict__ x,
                          const float* __restrict__ w1, const float* __restrict__ b1,
                          const float* __restrict__ w2, const float* __restrict__ b2,
                          float* __restrict__ y) {
    __shared__ float red[256];
    int row = blockIdx.x;
    int tid = threadIdx.x;
    const float* xr = x + (size_t)row * D_MODEL;
    float v0 = xr[tid], v1 = xr[tid + 256], v2 = xr[tid + 512];

    red[tid] = v0 + v1 + v2;
    __syncthreads();
    for (int s = 128; s > 0; s >>= 1) { if (tid < s) red[tid] += red[tid + s]; __syncthreads(); }
    float mean = red[0] * (1.0f / D_MODEL);
    __syncthreads();
    float d0 = v0 - mean, d1 = v1 - mean, d2 = v2 - mean;
    red[tid] = d0 * d0 + d1 * d1 + d2 * d2;
    __syncthreads();
    for (int s = 128; s > 0; s >>= 1) { if (tid < s) red[tid] += red[tid + s]; __syncthreads(); }
    float rstd = rsqrtf(red[0] * (1.0f / D_MODEL) + 1e-5f);
    float y0 = d0 * rstd * w1[tid]       + b1[tid];
    float y1 = d1 * rstd * w1[tid + 256] + b1[tid + 256];
    float y2 = d2 * rstd * w1[tid + 512] + b1[tid + 512];

    if (DOUBLE) {
        __syncthreads();
        red[tid] = y0 + y1 + y2;
        __syncthreads();
        for (int s = 128; s > 0; s >>= 1) { if (tid < s) red[tid] += red[tid + s]; __syncthreads(); }
        float mean2 = red[0] * (1.0f / D_MODEL);
        __syncthreads();
        float e0 = y0 - mean2, e1 = y1 - mean2, e2 = y2 - mean2;
        red[tid] = e0 * e0 + e1 * e1 + e2 * e2;
        __syncthreads();
        for (int s = 128; s > 0; s >>= 1) { if (tid < s) red[tid] += red[tid + s]; __syncthreads(); }
        float rstd2 = rsqrtf(red[0] * (1.0f / D_MODEL) + 1e-5f);
        y0 = e0 * rstd2 * w2[tid]       + b2[tid];
        y1 = e1 * rstd2 * w2[tid + 256] + b2[tid + 256];
        y2 = e2 * rstd2 * w2[tid + 512] + b2[tid + 512];
    }
    float* yr = y + (size_t)row * D_MODEL;
    yr[tid] = y0; yr[tid + 256] = y1; yr[tid + 512] = y2;
}

// ---------------- TF32 tensor-core GEMM body ----------------
// Software-pipelined, double-buffered. A staged in MMA-fragment order with XOR
// swizzle so consumers read one LDS.128 per 16x16 A tile. B in k-major smem.
// A: [M,K] fp32 row-major (M%128==0, K%16==0).
// B: fp32 row-major [K,N] (N mult of 4 -> vector loads), or HEADED [N/64][K][64].
// NC: output width/stride (may be < N for padded-B case); epilogue clamps col<NC.
template <bool GELU, bool RESID, bool HEADED>
__device__ __forceinline__
void gemm_body(const float* __restrict__ A, const float* __restrict__ B,
               const float* __restrict__ bias, const float* __restrict__ resid,
               float* __restrict__ C, int M, int N, int K, int NC, int bn, int bm) {
    // A fragments: [buf][mi(8)][ks(2)][lane(32)][slot(4)]
    __shared__ unsigned Asf[2][8][2][32][4];
    __shared__ unsigned Bs[2][16][136];
    int tid = threadIdx.x;
    int lane = tid & 31, warp = tid >> 5;
    int wm = (warp & 1) * 64;       // warp row offset (2 warps along M)
    int wn = (warp >> 1) * 32;      // warp col offset (4 warps along N)
    int lr = lane >> 2;             // 0..7
    int lc = lane & 3;              // 0..3
    int lane_s = lr * 4 + (lc ^ ((lr >> 1) & 3));   // consumer swizzled lane

    float acc[4][4][4];
#pragma unroll
    for (int mi = 0; mi < 4; mi++)
#pragma unroll
        for (int ni = 0; ni < 4; ni++)
#pragma unroll
            for (int r = 0; r < 4; r++) acc[mi][ni][r] = 0.f;

    // ---- staging indices ----
    int arow_l = tid >> 1;                 // 0..127
    int aks    = tid & 1;                  // which ks half this thread stages
    int ami    = arow_l >> 4;              // A mtile
    int alr    = arow_l & 7;
    int ahi    = (arow_l >> 3) & 1;
    int asw    = (alr >> 1) & 3;           // staging swizzle
    int bkr    = tid >> 4;                 // 0..15
    int bnc    = (tid & 15) * 8;           // 0..120
    int bcol0  = bn * 128 + bnc;

    const float* aptr = A + (size_t)(bm * 128 + arow_l) * K + aks * 8;
    const float* bptr;
    if (HEADED) {
        int head = bcol0 >> 6;
        bptr = B + ((size_t)head * K + bkr) * 64 + (bcol0 & 63);
    } else {
        bptr = B + (size_t)bkr * N + bcol0;
    }

    float ar[8], br[8];

    auto load_tile = [&](int k0) {
        {
            const float* ap = aptr + k0;
            float4 v0 = *(const float4*)(ap);
            float4 v1 = *(const float4*)(ap + 4);
            ar[0]=v0.x; ar[1]=v0.y; ar[2]=v0.z; ar[3]=v0.w;
            ar[4]=v1.x; ar[5]=v1.y; ar[6]=v1.z; ar[7]=v1.w;
        }
        {
            const float* bp = HEADED ? (bptr + (size_t)k0 * 64)
                                     : (bptr + (size_t)k0 * N);
            float4 u0 = *(const float4*)(bp);
            float4 u1 = *(const float4*)(bp + 4);
            br[0]=u0.x; br[1]=u0.y; br[2]=u0.z; br[3]=u0.w;
            br[4]=u1.x; br[5]=u1.y; br[6]=u1.z; br[7]=u1.w;
        }
    };
    auto store_tile = [&](int buf) {
        unsigned* abase = &Asf[buf][ami][aks][0][0];
#pragma unroll
        for (int j = 0; j < 8; j++) {
            int ls   = alr * 4 + ((j & 3) ^ asw);
            int slot = ahi + 2 * (j >> 2);
            abase[ls * 4 + slot] = f2tf(ar[j]);
        }
        uint4 p0, p1;
        p0.x = f2tf(br[0]); p0.y = f2tf(br[1]); p0.z = f2tf(br[2]); p0.w = f2tf(br[3]);
        p1.x = f2tf(br[4]); p1.y = f2tf(br[5]); p1.z = f2tf(br[6]); p1.w = f2tf(br[7]);
        *(uint4*)&Bs[buf][bkr][bnc]     = p0;
        *(uint4*)&Bs[buf][bkr][bnc + 4] = p1;
    };

    load_tile(0);
    store_tile(0);
    __syncthreads();

    int cur = 0;
    for (int k0 = 0; k0 < K; k0 += 16) {
        bool has_next = (k0 + 16) < K;
        if (has_next) load_tile(k0 + 16);   // LDGs in flight during MMAs

#pragma unroll
        for (int ks = 0; ks < 2; ks++) {
            int kb = ks * 8;
            unsigned afr[4][4], bfr[4][2];
#pragma unroll
            for (int mi = 0; mi < 4; mi++) {
                int mig = (warp & 1) * 4 + mi;
                uint4 fa = *(const uint4*)&Asf[cur][mig][ks][lane_s][0];
                afr[mi][0] = fa.x; afr[mi][1] = fa.y;
                afr[mi][2] = fa.z; afr[mi][3] = fa.w;
            }
#pragma unroll
            for (int ni = 0; ni < 4; ni++) {
                int n0 = wn + ni * 8;
                bfr[ni][0] = Bs[cur][kb + lc][n0 + lr];
                bfr[ni][1] = Bs[cur][kb + lc + 4][n0 + lr];
            }
#pragma unroll
            for (int mi = 0; mi < 4; mi++)
#pragma unroll
                for (int ni = 0; ni < 4; ni++)
                    mma_tf32(acc[mi][ni], afr[mi], bfr[ni]);
        }

        if (has_next) store_tile(cur ^ 1);
        __syncthreads();
        cur ^= 1;
    }

    // ---- epilogue ----
#pragma unroll
    for (int mi = 0; mi < 4; mi++) {
        int row0 = bm * 128 + wm + mi * 16 + lr;
#pragma unroll
        for (int ni = 0; ni < 4; ni++) {
            int col = bn * 128 + wn + ni * 8 + lc * 2;
#pragma unroll
            for (int half = 0; half < 2; half++) {
                int row = row0 + half * 8;
#pragma unroll
                for (int cc = 0; cc < 2; cc++) {
                    int c = col + cc;
                    if (c < NC) {
                        float val = acc[mi][ni][half * 2 + cc] + bias[c];
                        if (GELU) val = 0.5f * val * (1.0f + erff(val * 0.70710678118654752f));
                        if (RESID) val += resid[(size_t)row * NC + c];
                        C[(size_t)row * NC + c] = val;
                    }
                }
            }
        }
    }
}

template <bool GELU, bool RESID, bool HEADED>
__global__ __launch_bounds__(256, 2)
void gemm_kernel(const float* __restrict__ A, const float* __restrict__ B,
                 const float* __restrict__ bias, const float* __restrict__ resid,
                 float* __restrict__ C, int M, int N, int K, int NC) {
    gemm_body<GELU, RESID, HEADED>(A, B, bias, resid, C, M, N, K, NC,
                                   blockIdx.x, blockIdx.y);
}

// Fused Q/K/V projection: blockIdx.z selects which of the three GEMMs.
__global__ __launch_bounds__(256, 2)
void qkv_kernel(const float* __restrict__ A,
                const float* __restrict__ Wq, const float* __restrict__ Wk,
                const float* __restrict__ Wv,
                const float* __restrict__ bq, const float* __restrict__ bk,
                const float* __restrict__ bv,
                float* __restrict__ q, float* __restrict__ k, float* __restrict__ v) {
    const float* B    = (blockIdx.z == 0) ? Wq : (blockIdx.z == 1) ? Wk : Wv;
    const float* bias = (blockIdx.z == 0) ? bq : (blockIdx.z == 1) ? bk : bv;
    float*       C    = (blockIdx.z == 0) ? q  : (blockIdx.z == 1) ? k  : v;
    gemm_body<false, false, true>(A, B, bias, nullptr, C,
                                  ROWS, D_MODEL, D_MODEL, D_MODEL, blockIdx.x, blockIdx.y);
}

// ---------------- fused causal attention (flash-style, 64-row query tiles) ----------------
// Smem tiles stored as float4 chunks with XOR swizzle:
//   chunk(row, e4) = row*16 + (e4 ^ ((row>>2)&7)), conflict-free for all access patterns.
#define ATT_SMEM (3 * 1024 * 16)
__device__ __forceinline__ int chnk(int row, int e4) {
    return row * 16 + (e4 ^ ((row >> 2) & 7));
}

__global__ __launch_bounds__(256)
void attn_kernel(const float* __restrict__ q, const float* __restrict__ k,
                 const float* __restrict__ v, float* __restrict__ o) {
    extern __shared__ float4 sm4[];
    float4* qs = sm4;            // 64 rows x 16 chunks
    float4* ks = sm4 + 1024;     // (reused as p)
    float4* vs = sm4 + 2048;
    int qi = blockIdx.x, hh = blockIdx.y, b = blockIdx.z;
    int tid = threadIdx.x, tx = tid & 15, ty = tid >> 4;
    const size_t base = ((size_t)b * SEQ) * D_MODEL + (size_t)hh * HEAD_DIM;
    const float inv_scale = 0.03608439182435161f;   // 1/sqrt(768)

    // stage q tile (4 chunks per thread)
#pragma unroll
    for (int i = 0; i < 4; i++) {
        int id = tid + 256 * i;
        int r = id >> 4, e4 = id & 15;
        qs[chnk(r, e4)] = *(const float4*)(q + base + (size_t)(qi * 64 + r) * D_MODEL + e4 * 4);
    }

    float m_[4], l_[4], acc[4][4];
#pragma unroll
    for (int r = 0; r < 4; r++) {
        m_[r] = -1e30f; l_[r] = 0.f;
#pragma unroll
        for (int c = 0; c < 4; c++) acc[r][c] = 0.f;
    }

    for (int j = 0; j <= qi; j++) {
        __syncthreads();
#pragma unroll
        for (int i = 0; i < 4; i++) {
            int id = tid + 256 * i;
            int r = id >> 4, e4 = id & 15;
            size_t goff = base + (size_t)(j * 64 + r) * D_MODEL + e4 * 4;
            ks[chnk(r, e4)] = *(const float4*)(k + goff);
            vs[chnk(r, e4)] = *(const float4*)(v + goff);
        }
        __syncthreads();

        float s[4][4];
#pragma unroll
        for (int r = 0; r < 4; r++)
#pragma unroll
            for (int c = 0; c < 4; c++) s[r][c] = 0.f;

#pragma unroll 4
        for (int e4 = 0; e4 < 16; e4++) {
            float4 qv[4], kv[4];
#pragma unroll
            for (int r = 0; r < 4; r++) qv[r] = qs[chnk(ty * 4 + r, e4)];
#pragma unroll
            for (int c = 0; c < 4; c++) kv[c] = ks[chnk(tx * 4 + c, e4)];
#pragma unroll
            for (int r = 0; r < 4; r++)
#pragma unroll
                for (int c = 0; c < 4; c++) {
                    s[r][c] += qv[r].x * kv[c].x;
                    s[r][c] += qv[r].y * kv[c].y;
                    s[r][c] += qv[r].z * kv[c].z;
                    s[r][c] += qv[r].w * kv[c].w;
                }
        }

#pragma unroll
        for (int r = 0; r < 4; r++)
#pragma unroll
            for (int c = 0; c < 4; c++) {
                s[r][c] *= inv_scale;
                if (j == qi && (tx * 4 + c) > (ty * 4 + r)) s[r][c] = -1e30f;
            }

#pragma unroll
        for (int r = 0; r < 4; r++) {
            float rm = fmaxf(fmaxf(s[r][0], s[r][1]), fmaxf(s[r][2], s[r][3]));
#pragma unroll
            for (int off = 1; off < 16; off <<= 1)
                rm = fmaxf(rm, __shfl_xor_sync(0xffffffffu, rm, off));
            float mnew = fmaxf(m_[r], rm);
            float alpha = __expf(m_[r] - mnew);
            float psum = 0.f;
#pragma unroll
            for (int c = 0; c < 4; c++) { float p = __expf(s[r][c] - mnew); s[r][c] = p; psum += p; }
#pragma unroll
            for (int off = 1; off < 16; off <<= 1)
                psum += __shfl_xor_sync(0xffffffffu, psum, off);
            l_[r] = l_[r] * alpha + psum;
            m_[r] = mnew;
#pragma unroll
            for (int c = 0; c < 4; c++) acc[r][c] *= alpha;
        }

        __syncthreads();   // all ks reads done -> safe to overwrite with p
#pragma unroll
        for (int r = 0; r < 4; r++)
            ks[chnk(ty * 4 + r, tx)] = make_float4(s[r][0], s[r][1], s[r][2], s[r][3]);
        __syncthreads();

#pragma unroll 4
        for (int k4 = 0; k4 < 16; k4++) {
            float4 pv[4], vv[4];
#pragma unroll
            for (int r = 0; r < 4; r++) pv[r] = ks[chnk(ty * 4 + r, k4)];
#pragma unroll
            for (int kk = 0; kk < 4; kk++) vv[kk] = vs[chnk(k4 * 4 + kk, tx)];
#pragma unroll
            for (int r = 0; r < 4; r++) {
                acc[r][0] += pv[r].x * vv[0].x; acc[r][1] += pv[r].x * vv[0].y;
                acc[r][2] += pv[r].x * vv[0].z; acc[r][3] += pv[r].x * vv[0].w;
                acc[r][0] += pv[r].y * vv[1].x; acc[r][1] += pv[r].y * vv[1].y;
                acc[r][2] += pv[r].y * vv[1].z; acc[r][3] += pv[r].y * vv[1].w;
                acc[r][0] += pv[r].z * vv[2].x; acc[r][1] += pv[r].z * vv[2].y;
                acc[r][2] += pv[r].z * vv[2].z; acc[r][3] += pv[r].z * vv[2].w;
                acc[r][0] += pv[r].w * vv[3].x; acc[r][1] += pv[r].w * vv[3].y;
                acc[r][2] += pv[r].w * vv[3].z; acc[r][3] += pv[r].w * vv[3].w;
            }
        }
    }

#pragma unroll
    for (int r = 0; r < 4; r++) {
        float invl = 1.0f / l_[r];
#pragma unroll
        for (int c = 0; c < 4; c++)
            o[base + (size_t)(qi * 64 + ty * 4 + r) * D_MODEL + tx * 4 + c] = acc[r][c] * invl;
    }
}

// ---------------- launch ----------------
extern "C" void kernel_launch(void* const* d_in, const int* in_sizes, int n_in,
                              void* d_out, int out_size) {
    const int*   x      = (const int*)  d_in[0];
    const float* wte    = (const float*)d_in[1];
    const float* wpe    = (const float*)d_in[2];
    const float* ln1_w  = (const float*)d_in[3];
    const float* ln1_b  = (const float*)d_in[4];
    const float* Wq     = (const float*)d_in[5];
    const float* bq     = (const float*)d_in[6];
    const float* Wk     = (const float*)d_in[7];
    const float* bk     = (const float*)d_in[8];
    const float* Wv     = (const float*)d_in[9];
    const float* bv     = (const float*)d_in[10];
    const float* Wp     = (const float*)d_in[11];
    const float* bp     = (const float*)d_in[12];
    const float* ln2_w  = (const float*)d_in[13];
    const float* ln2_b  = (const float*)d_in[14];
    const float* lnfc_w = (const float*)d_in[15];
    const float* lnfc_b = (const float*)d_in[16];
    const float* W1     = (const float*)d_in[17];
    const float* b1     = (const float*)d_in[18];
    const float* W2     = (const float*)d_in[19];
    const float* b2     = (const float*)d_in[20];
    const float* lnf_w  = (const float*)d_in[21];
    const float* lnf_b  = (const float*)d_in[22];
    const float* Wh     = (const float*)d_in[23];
    const float* bh     = (const float*)d_in[24];
    float* out = (float*)d_out;

    float *h, *a, *q, *k, *v, *o, *m, *whp;
    cudaGetSymbolAddress((void**)&h, g_h);
    cudaGetSymbolAddress((void**)&a, g_a);
    cudaGetSymbolAddress((void**)&q, g_q);
    cudaGetSymbolAddress((void**)&k, g_k);
    cudaGetSymbolAddress((void**)&v, g_v);
    cudaGetSymbolAddress((void**)&o, g_o);
    cudaGetSymbolAddress((void**)&m, g_m);
    cudaGetSymbolAddress((void**)&whp, g_whp);

    cudaFuncSetAttribute(attn_kernel, cudaFuncAttributeMaxDynamicSharedMemorySize, ATT_SMEM);

    embed_kernel<<<ROWS, 256>>>(x, wte, wpe, h);
    pad_wh_kernel<<<dim3((VOCAB_P + 255) / 256, D_MODEL), 256>>>(Wh, whp);

    dim3 gQKV((D_MODEL + 127) / 128, ROWS / 128, 3);  // (6, 32, 3)
    dim3 gProj((D_MODEL + 127) / 128, ROWS / 128);    // (6, 32)
    dim3 gFF1((D_FF + 127) / 128, ROWS / 128);        // (24, 32)
    dim3 gHead(VOCAB_P / 128, ROWS / 128);            // (393, 32)
    dim3 gAttn(SEQ / 64, N_HEADS, BATCH);             // (16, 12, 4)

    for (int l = 0; l < N_LAYERS; l++) {
        const float* Wq_l = Wq + (size_t)l * N_HEADS * D_MODEL * HEAD_DIM;
        const float* Wk_l = Wk + (size_t)l * N_HEADS * D_MODEL * HEAD_DIM;
        const float* Wv_l = Wv + (size_t)l * N_HEADS * D_MODEL * HEAD_DIM;
        const float* Wp_l = Wp + (size_t)l * D_MODEL * D_MODEL;
        const float* W1_l = W1 + (size_t)l * D_MODEL * D_FF;
        const float* W2_l = W2 + (size_t)l * D_FF * D_MODEL;

        ln_kernel<false><<<ROWS, 256>>>(h, ln1_w + l * D_MODEL, ln1_b + l * D_MODEL,
                                        nullptr, nullptr, a);

        qkv_kernel<<<gQKV, 256>>>(a, Wq_l, Wk_l, Wv_l,
                                  bq + l * D_MODEL, bk + l * D_MODEL, bv + l * D_MODEL,
                                  q, k, v);

        attn_kernel<<<gAttn, 256, ATT_SMEM>>>(q, k, v, o);

        gemm_kernel<false, true, false><<<gProj, 256>>>(o, Wp_l, bp + l * D_MODEL, h, h,
                                                        ROWS, D_MODEL, D_MODEL, D_MODEL);

        ln_kernel<true><<<ROWS, 256>>>(h, ln2_w + l * D_MODEL, ln2_b + l * D_MODEL,
                                       lnfc_w + l * D_MODEL, lnfc_b + l * D_MODEL, a);

        gemm_kernel<true, false, false><<<gFF1, 256>>>(a, W1_l, b1 + l * D_FF, nullptr, m,
                                                       ROWS, D_FF, D_MODEL, D_FF);
        gemm_kernel<false, true, false><<<gProj, 256>>>(m, W2_l, b2 + l * D_MODEL, h, h,
                                                        ROWS, D_MODEL, D_FF, D_MODEL);
    }

    ln_kernel<false><<<ROWS, 256>>>(h, lnf_w, lnf_b, nullptr, nullptr, a);
    gemm_kernel<false, false, false><<<gHead, 256>>>(a, whp, bh, nullptr, out,
                                                     ROWS, VOCAB_P, D_MODEL, VOCAB);
}

// round 7
// speedup vs baseline: 2.6056x; 1.0064x over previous
#include <cuda_runtime.h>
#include <cuda_bf16.h>
#include <math.h>

#define D_MODEL 768
#define N_HEADS 12
#define HEAD_DIM 64
#define N_LAYERS 12
#define SEQ 1024
#define BATCH 4
#define ROWS (BATCH * SEQ)       // 4096
#define D_FF (4 * D_MODEL)       // 3072
#define VOCAB 50257
#define VOCAB_P 50432            // padded to multiple of 256

// ---------------- scratch (device globals; no allocation allowed) ----------------
__device__ float g_h[ROWS * D_MODEL];
__device__ float g_a[ROWS * D_MODEL];
__device__ float g_q[ROWS * D_MODEL];
__device__ float g_k[ROWS * D_MODEL];
__device__ float g_v[ROWS * D_MODEL];
__device__ float g_o[ROWS * D_MODEL];
__device__ float g_m[ROWS * D_FF];
__device__ float g_whp[D_MODEL * VOCAB_P];   // padded LM head weight

// ---------------- helpers ----------------
__device__ __forceinline__ unsigned f2tf(float x) {
    unsigned r;
    asm("cvt.rna.tf32.f32 %0, %1;" : "=r"(r) : "f"(x));
    return r;
}

__device__ __forceinline__ void mma_tf32(float* c, const unsigned* a, const unsigned* b) {
    asm volatile(
        "mma.sync.aligned.m16n8k8.row.col.f32.tf32.tf32.f32 "
        "{%0,%1,%2,%3}, {%4,%5,%6,%7}, {%8,%9}, {%0,%1,%2,%3};"
        : "+f"(c[0]), "+f"(c[1]), "+f"(c[2]), "+f"(c[3])
        : "r"(a[0]), "r"(a[1]), "r"(a[2]), "r"(a[3]), "r"(b[0]), "r"(b[1]));
}

// ---------------- embedding ----------------
__global__ void embed_kernel(const int* __restrict__ x, const float* __restrict__ wte,
                             const float* __restrict__ wpe, float* __restrict__ h) {
    int row = blockIdx.x;            // 0..4095
    int tok = x[row];
    int s = row & (SEQ - 1);
    const float* te = wte + (size_t)tok * D_MODEL;
    const float* pe = wpe + (size_t)s * D_MODEL;
    float* out = h + (size_t)row * D_MODEL;
    for (int d = threadIdx.x; d < D_MODEL; d += 256)
        out[d] = te[d] + pe[d];
}

// ---------------- pad LM head weight ----------------
__global__ void pad_wh_kernel(const float* __restrict__ Wh, float* __restrict__ WhP) {
    int row = blockIdx.y;
    int col = blockIdx.x * 256 + threadIdx.x;
    if (col < VOCAB_P)
        WhP[(size_t)row * VOCAB_P + col] =
            (col < VOCAB) ? Wh[(size_t)row * VOCAB + col] : 0.f;
}

// ---------------- layernorm (single or fused double) ----------------
template <bool DOUBLE>
__global__ void ln_kernel(const float* __restrict__ x,
                          const float* __restrict__ w1, const float* __restrict__ b1,
                          const float* __restrict__ w2, const float* __restrict__ b2,
                          float* __restrict__ y) {
    __shared__ float red[256];
    int row = blockIdx.x;
    int tid = threadIdx.x;
    const float* xr = x + (size_t)row * D_MODEL;
    float v0 = xr[tid], v1 = xr[tid + 256], v2 = xr[tid + 512];

    red[tid] = v0 + v1 + v2;
    __syncthreads();
    for (int s = 128; s > 0; s >>= 1) { if (tid < s) red[tid] += red[tid + s]; __syncthreads(); }
    float mean = red[0] * (1.0f / D_MODEL);
    __syncthreads();
    float d0 = v0 - mean, d1 = v1 - mean, d2 = v2 - mean;
    red[tid] = d0 * d0 + d1 * d1 + d2 * d2;
    __syncthreads();
    for (int s = 128; s > 0; s >>= 1) { if (tid < s) red[tid] += red[tid + s]; __syncthreads(); }
    float rstd = rsqrtf(red[0] * (1.0f / D_MODEL) + 1e-5f);
    float y0 = d0 * rstd * w1[tid]       + b1[tid];
    float y1 = d1 * rstd * w1[tid + 256] + b1[tid + 256];
    float y2 = d2 * rstd * w1[tid + 512] + b1[tid + 512];

    if (DOUBLE) {
        __syncthreads();
        red[tid] = y0 + y1 + y2;
        __syncthreads();
        for (int s = 128; s > 0; s >>= 1) { if (tid < s) red[tid] += red[tid + s]; __syncthreads(); }
        float mean2 = red[0] * (1.0f / D_MODEL);
        __syncthreads();
        float e0 = y0 - mean2, e1 = y1 - mean2, e2 = y2 - mean2;
        red[tid] = e0 * e0 + e1 * e1 + e2 * e2;
        __syncthreads();
        for (int s = 128; s > 0; s >>= 1) { if (tid < s) red[tid] += red[tid + s]; __syncthreads(); }
        float rstd2 = rsqrtf(red[0] * (1.0f / D_MODEL) + 1e-5f);
        y0 = e0 * rstd2 * w2[tid]       + b2[tid];
        y1 = e1 * rstd2 * w2[tid + 256] + b2[tid + 256];
        y2 = e2 * rstd2 * w2[tid + 512] + b2[tid + 512];
    }
    float* yr = y + (size_t)row * D_MODEL;
    yr[tid] = y0; yr[tid + 256] = y1; yr[tid + 512] = y2;
}

// ---------------- TF32 tensor-core GEMM body (128x256 tile) ----------------
// 8 warps, warp tile 64x64 (4 mi x 8 ni m16n8k8), software-pipelined double buffer.
// A: [M,K] fp32 row-major (M%128==0, K%16==0).
// B: fp32 row-major [K,N] (N mult of 256), or HEADED [N/64][K][64] (qkv; 4 heads/bn).
// NC: output width/stride (may be < N for padded-B); epilogue clamps col<NC.
template <bool GELU, bool RESID, bool HEADED>
__device__ __forceinline__
void gemm_body(const float* __restrict__ A, const float* __restrict__ B,
               const float* __restrict__ bias, const float* __restrict__ resid,
               float* __restrict__ C, int M, int N, int K, int NC, int bn, int bm) {
    // A fragments: [buf][mi(8)][ks(2)][lane(32)][slot(4)]
    __shared__ unsigned Asf[2][8][2][32][4];
    __shared__ unsigned Bs[2][16][264];      // k-major, 256 cols + pad
    int tid = threadIdx.x;
    int lane = tid & 31, warp = tid >> 5;
    int wm = (warp & 1) * 64;       // warp row offset (2 warps along M)
    int wn = (warp >> 1) * 64;      // warp col offset (4 warps along N, 64 each)
    int lr = lane >> 2;             // 0..7
    int lc = lane & 3;              // 0..3
    int lane_s = lr * 4 + (lc ^ ((lr >> 1) & 3));   // consumer swizzled lane

    float acc[4][8][4];
#pragma unroll
    for (int mi = 0; mi < 4; mi++)
#pragma unroll
        for (int ni = 0; ni < 8; ni++)
#pragma unroll
            for (int r = 0; r < 4; r++) acc[mi][ni][r] = 0.f;

    // ---- staging indices ----
    int arow_l = tid >> 1;                 // 0..127
    int aks    = tid & 1;                  // which ks half this thread stages
    int ami    = arow_l >> 4;              // A mtile
    int alr    = arow_l & 7;
    int ahi    = (arow_l >> 3) & 1;
    int asw    = (alr >> 1) & 3;           // staging swizzle
    int bkr    = tid >> 4;                 // 0..15 (k row)
    int bcl    = (tid & 15) * 4;           // 0..60 (col within 64-chunk)

    const float* aptr = A + (size_t)(bm * 128 + arow_l) * K + aks * 8;
    const float* bptr[4];
    int strideB;
    if (HEADED) {
        strideB = 64;
#pragma unroll
        for (int c = 0; c < 4; c++)
            bptr[c] = B + ((size_t)(bn * 4 + c) * K + bkr) * 64 + bcl;
    } else {
        strideB = N;
#pragma unroll
        for (int c = 0; c < 4; c++)
            bptr[c] = B + (size_t)bkr * N + bn * 256 + c * 64 + bcl;
    }

    float ar[8];
    float4 br4[4];

    auto load_tile = [&](int k0) {
        {
            const float* ap = aptr + k0;
            float4 v0 = *(const float4*)(ap);
            float4 v1 = *(const float4*)(ap + 4);
            ar[0]=v0.x; ar[1]=v0.y; ar[2]=v0.z; ar[3]=v0.w;
            ar[4]=v1.x; ar[5]=v1.y; ar[6]=v1.z; ar[7]=v1.w;
        }
#pragma unroll
        for (int c = 0; c < 4; c++)
            br4[c] = *(const float4*)(bptr[c] + (size_t)k0 * strideB);
    };
    auto store_tile = [&](int buf) {
        unsigned* abase = &Asf[buf][ami][aks][0][0];
#pragma unroll
        for (int j = 0; j < 8; j++) {
            int ls   = alr * 4 + ((j & 3) ^ asw);
            int slot = ahi + 2 * (j >> 2);
            abase[ls * 4 + slot] = f2tf(ar[j]);
        }
#pragma unroll
        for (int c = 0; c < 4; c++) {
            uint4 p;
            p.x = f2tf(br4[c].x); p.y = f2tf(br4[c].y);
            p.z = f2tf(br4[c].z); p.w = f2tf(br4[c].w);
            *(uint4*)&Bs[buf][bkr][c * 64 + bcl] = p;
        }
    };

    load_tile(0);
    store_tile(0);
    __syncthreads();

    int cur = 0;
    for (int k0 = 0; k0 < K; k0 += 16) {
        bool has_next = (k0 + 16) < K;
        if (has_next) load_tile(k0 + 16);   // LDGs in flight during MMAs

#pragma unroll
        for (int ks = 0; ks < 2; ks++) {
            int kb = ks * 8;
            unsigned afr[4][4], bfr[8][2];
#pragma unroll
            for (int mi = 0; mi < 4; mi++) {
                int mig = (warp & 1) * 4 + mi;
                uint4 fa = *(const uint4*)&Asf[cur][mig][ks][lane_s][0];
                afr[mi][0] = fa.x; afr[mi][1] = fa.y;
                afr[mi][2] = fa.z; afr[mi][3] = fa.w;
            }
#pragma unroll
            for (int ni = 0; ni < 8; ni++) {
                int n0 = wn + ni * 8;
                bfr[ni][0] = Bs[cur][kb + lc][n0 + lr];
                bfr[ni][1] = Bs[cur][kb + lc + 4][n0 + lr];
            }
#pragma unroll
            for (int mi = 0; mi < 4; mi++)
#pragma unroll
                for (int ni = 0; ni < 8; ni++)
                    mma_tf32(acc[mi][ni], afr[mi], bfr[ni]);
        }

        if (has_next) store_tile(cur ^ 1);
        __syncthreads();
        cur ^= 1;
    }

    // ---- epilogue ----
#pragma unroll
    for (int mi = 0; mi < 4; mi++) {
        int row0 = bm * 128 + wm + mi * 16 + lr;
#pragma unroll
        for (int ni = 0; ni < 8; ni++) {
            int col = bn * 256 + wn + ni * 8 + lc * 2;
#pragma unroll
            for (int half = 0; half < 2; half++) {
                int row = row0 + half * 8;
#pragma unroll
                for (int cc = 0; cc < 2; cc++) {
                    int c = col + cc;
                    if (c < NC) {
                        float val = acc[mi][ni][half * 2 + cc] + bias[c];
                        if (GELU) val = 0.5f * val * (1.0f + erff(val * 0.70710678118654752f));
                        if (RESID) val += resid[(size_t)row * NC + c];
                        C[(size_t)row * NC + c] = val;
                    }
                }
            }
        }
    }
}

template <bool GELU, bool RESID, bool HEADED>
__global__ __launch_bounds__(256, 1)
void gemm_kernel(const float* __restrict__ A, const float* __restrict__ B,
                 const float* __restrict__ bias, const float* __restrict__ resid,
                 float* __restrict__ C, int M, int N, int K, int NC) {
    gemm_body<GELU, RESID, HEADED>(A, B, bias, resid, C, M, N, K, NC,
                                   blockIdx.x, blockIdx.y);
}

// Fused Q/K/V projection: blockIdx.z selects which of the three GEMMs.
__global__ __launch_bounds__(256, 1)
void qkv_kernel(const float* __restrict__ A,
                const float* __restrict__ Wq, const float* __restrict__ Wk,
                const float* __restrict__ Wv,
                const float* __restrict__ bq, const float* __restrict__ bk,
                const float* __restrict__ bv,
                float* __restrict__ q, float* __restrict__ k, float* __restrict__ v) {
    const float* B    = (blockIdx.z == 0) ? Wq : (blockIdx.z == 1) ? Wk : Wv;
    const float* bias = (blockIdx.z == 0) ? bq : (blockIdx.z == 1) ? bk : bv;
    float*       C    = (blockIdx.z == 0) ? q  : (blockIdx.z == 1) ? k  : v;
    gemm_body<false, false, true>(A, B, bias, nullptr, C,
                                  ROWS, D_MODEL, D_MODEL, D_MODEL, blockIdx.x, blockIdx.y);
}

// ---------------- fused causal attention (flash-style, 64-row query tiles) ----------------
// Smem float4 chunks with XOR swizzle; K/V tile j+1 prefetched into registers
// while tile j computes (LDG latency hidden).
#define ATT_SMEM (3 * 1024 * 16)
__device__ __forceinline__ int chnk(int row, int e4) {
    return row * 16 + (e4 ^ ((row >> 2) & 7));
}

__global__ __launch_bounds__(256, 2)
void attn_kernel(const float* __restrict__ q, const float* __restrict__ k,
                 const float* __restrict__ v, float* __restrict__ o) {
    extern __shared__ float4 sm4[];
    float4* qs = sm4;            // 64 rows x 16 chunks
    float4* ks = sm4 + 1024;     // (reused as p)
    float4* vs = sm4 + 2048;
    int qi = blockIdx.x, hh = blockIdx.y, b = blockIdx.z;
    int tid = threadIdx.x, tx = tid & 15, ty = tid >> 4;
    const size_t base = ((size_t)b * SEQ) * D_MODEL + (size_t)hh * HEAD_DIM;
    const float inv_scale = 0.03608439182435161f;   // 1/sqrt(768)

    int str = tid >> 4;        // staging row base (x4)
    int se4 = tid & 15;        // staging chunk col

    // stage q tile (4 chunks per thread)
#pragma unroll
    for (int i = 0; i < 4; i++) {
        int r = str + 16 * i;
        qs[chnk(r, se4)] = *(const float4*)(q + base + (size_t)(qi * 64 + r) * D_MODEL + se4 * 4);
    }

    // prefetch K/V tile j=0
    float4 kr[4], vr[4];
#pragma unroll
    for (int i = 0; i < 4; i++) {
        int r = str + 16 * i;
        size_t goff = base + (size_t)r * D_MODEL + se4 * 4;
        kr[i] = *(const float4*)(k + goff);
        vr[i] = *(const float4*)(v + goff);
    }

    float m_[4], l_[4], acc[4][4];
#pragma unroll
    for (int r = 0; r < 4; r++) {
        m_[r] = -1e30f; l_[r] = 0.f;
#pragma unroll
        for (int c = 0; c < 4; c++) acc[r][c] = 0.f;
    }

    for (int j = 0; j <= qi; j++) {
        __syncthreads();   // prior PV reads done; qs staged (first iter)
#pragma unroll
        for (int i = 0; i < 4; i++) {
            int r = str + 16 * i;
            ks[chnk(r, se4)] = kr[i];
            vs[chnk(r, se4)] = vr[i];
        }
        if (j < qi) {      // prefetch next tile; latency covered by QK+softmax+PV
#pragma unroll
            for (int i = 0; i < 4; i++) {
                int r = str + 16 * i;
                size_t goff = base + (size_t)((j + 1) * 64 + r) * D_MODEL + se4 * 4;
                kr[i] = *(const float4*)(k + goff);
                vr[i] = *(const float4*)(v + goff);
            }
        }
        __syncthreads();

        float s[4][4];
#pragma unroll
        for (int r = 0; r < 4; r++)
#pragma unroll
            for (int c = 0; c < 4; c++) s[r][c] = 0.f;

#pragma unroll 4
        for (int e4 = 0; e4 < 16; e4++) {
            float4 qv[4], kv[4];
#pragma unroll
            for (int r = 0; r < 4; r++) qv[r] = qs[chnk(ty * 4 + r, e4)];
#pragma unroll
            for (int c = 0; c < 4; c++) kv[c] = ks[chnk(tx * 4 + c, e4)];
#pragma unroll
            for (int r = 0; r < 4; r++)
#pragma unroll
                for (int c = 0; c < 4; c++) {
                    s[r][c] += qv[r].x * kv[c].x;
                    s[r][c] += qv[r].y * kv[c].y;
                    s[r][c] += qv[r].z * kv[c].z;
                    s[r][c] += qv[r].w * kv[c].w;
                }
        }

#pragma unroll
        for (int r = 0; r < 4; r++)
#pragma unroll
            for (int c = 0; c < 4; c++) {
                s[r][c] *= inv_scale;
                if (j == qi && (tx * 4 + c) > (ty * 4 + r)) s[r][c] = -1e30f;
            }

#pragma unroll
        for (int r = 0; r < 4; r++) {
            float rm = fmaxf(fmaxf(s[r][0], s[r][1]), fmaxf(s[r][2], s[r][3]));
#pragma unroll
            for (int off = 1; off < 16; off <<= 1)
                rm = fmaxf(rm, __shfl_xor_sync(0xffffffffu, rm, off));
            float mnew = fmaxf(m_[r], rm);
            float alpha = __expf(m_[r] - mnew);
            float psum = 0.f;
#pragma unroll
            for (int c = 0; c < 4; c++) { float p = __expf(s[r][c] - mnew); s[r][c] = p; psum += p; }
#pragma unroll
            for (int off = 1; off < 16; off <<= 1)
                psum += __shfl_xor_sync(0xffffffffu, psum, off);
            l_[r] = l_[r] * alpha + psum;
            m_[r] = mnew;
#pragma unroll
            for (int c = 0; c < 4; c++) acc[r][c] *= alpha;
        }

        __syncthreads();   // all ks reads done -> safe to overwrite with p
#pragma unroll
        for (int r = 0; r < 4; r++)
            ks[chnk(ty * 4 + r, tx)] = make_float4(s[r][0], s[r][1], s[r][2], s[r][3]);
        __syncthreads();

#pragma unroll 4
        for (int k4 = 0; k4 < 16; k4++) {
            float4 pv[4], vv[4];
#pragma unroll
            for (int r = 0; r < 4; r++) pv[r] = ks[chnk(ty * 4 + r, k4)];
#pragma unroll
            for (int kk = 0; kk < 4; kk++) vv[kk] = vs[chnk(k4 * 4 + kk, tx)];
#pragma unroll
            for (int r = 0; r < 4; r++) {
                acc[r][0] += pv[r].x * vv[0].x; acc[r][1] += pv[r].x * vv[0].y;
                acc[r][2] += pv[r].x * vv[0].z; acc[r][3] += pv[r].x * vv[0].w;
                acc[r][0] += pv[r].y * vv[1].x; acc[r][1] += pv[r].y * vv[1].y;
                acc[r][2] += pv[r].y * vv[1].z; acc[r][3] += pv[r].y * vv[1].w;
                acc[r][0] += pv[r].z * vv[2].x; acc[r][1] += pv[r].z * vv[2].y;
                acc[r][2] += pv[r].z * vv[2].z; acc[r][3] += pv[r].z * vv[2].w;
                acc[r][0] += pv[r].w * vv[3].x; acc[r][1] += pv[r].w * vv[3].y;
                acc[r][2] += pv[r].w * vv[3].z; acc[r][3] += pv[r].w * vv[3].w;
            }
        }
    }

#pragma unroll
    for (int r = 0; r < 4; r++) {
        float invl = 1.0f / l_[r];
#pragma unroll
        for (int c = 0; c < 4; c++)
            o[base + (size_t)(qi * 64 + ty * 4 + r) * D_MODEL + tx * 4 + c] = acc[r][c] * invl;
    }
}

// ---------------- launch ----------------
extern "C" void kernel_launch(void* const* d_in, const int* in_sizes, int n_in,
                              void* d_out, int out_size) {
    const int*   x      = (const int*)  d_in[0];
    const float* wte    = (const float*)d_in[1];
    const float* wpe    = (const float*)d_in[2];
    const float* ln1_w  = (const float*)d_in[3];
    const float* ln1_b  = (const float*)d_in[4];
    const float* Wq     = (const float*)d_in[5];
    const float* bq     = (const float*)d_in[6];
    const float* Wk     = (const float*)d_in[7];
    const float* bk     = (const float*)d_in[8];
    const float* Wv     = (const float*)d_in[9];
    const float* bv     = (const float*)d_in[10];
    const float* Wp     = (const float*)d_in[11];
    const float* bp     = (const float*)d_in[12];
    const float* ln2_w  = (const float*)d_in[13];
    const float* ln2_b  = (const float*)d_in[14];
    const float* lnfc_w = (const float*)d_in[15];
    const float* lnfc_b = (const float*)d_in[16];
    const float* W1     = (const float*)d_in[17];
    const float* b1     = (const float*)d_in[18];
    const float* W2     = (const float*)d_in[19];
    const float* b2     = (const float*)d_in[20];
    const float* lnf_w  = (const float*)d_in[21];
    const float* lnf_b  = (const float*)d_in[22];
    const float* Wh     = (const float*)d_in[23];
    const float* bh     = (const float*)d_in[24];
    float* out = (float*)d_out;

    float *h, *a, *q, *k, *v, *o, *m, *whp;
    cudaGetSymbolAddress((void**)&h, g_h);
    cudaGetSymbolAddress((void**)&a, g_a);
    cudaGetSymbolAddress((void**)&q, g_q);
    cudaGetSymbolAddress((void**)&k, g_k);
    cudaGetSymbolAddress((void**)&v, g_v);
    cudaGetSymbolAddress((void**)&o, g_o);
    cudaGetSymbolAddress((void**)&m, g_m);
    cudaGetSymbolAddress((void**)&whp, g_whp);

    cudaFuncSetAttribute(attn_kernel, cudaFuncAttributeMaxDynamicSharedMemorySize, ATT_SMEM);

    embed_kernel<<<ROWS, 256>>>(x, wte, wpe, h);
    pad_wh_kernel<<<dim3((VOCAB_P + 255) / 256, D_MODEL), 256>>>(Wh, whp);

    dim3 gQKV(D_MODEL / 256, ROWS / 128, 3);          // (3, 32, 3)
    dim3 gProj(D_MODEL / 256, ROWS / 128);            // (3, 32)
    dim3 gFF1(D_FF / 256, ROWS / 128);                // (12, 32)
    dim3 gHead(VOCAB_P / 256, ROWS / 128);            // (197, 32)
    dim3 gAttn(SEQ / 64, N_HEADS, BATCH);             // (16, 12, 4)

    for (int l = 0; l < N_LAYERS; l++) {
        const float* Wq_l = Wq + (size_t)l * N_HEADS * D_MODEL * HEAD_DIM;
        const float* Wk_l = Wk + (size_t)l * N_HEADS * D_MODEL * HEAD_DIM;
        const float* Wv_l = Wv + (size_t)l * N_HEADS * D_MODEL * HEAD_DIM;
        const float* Wp_l = Wp + (size_t)l * D_MODEL * D_MODEL;
        const float* W1_l = W1 + (size_t)l * D_MODEL * D_FF;
        const float* W2_l = W2 + (size_t)l * D_FF * D_MODEL;

        ln_kernel<false><<<ROWS, 256>>>(h, ln1_w + l * D_MODEL, ln1_b + l * D_MODEL,
                                        nullptr, nullptr, a);

        qkv_kernel<<<gQKV, 256>>>(a, Wq_l, Wk_l, Wv_l,
                                  bq + l * D_MODEL, bk + l * D_MODEL, bv + l * D_MODEL,
                                  q, k, v);

        attn_kernel<<<gAttn, 256, ATT_SMEM>>>(q, k, v, o);

        gemm_kernel<false, true, false><<<gProj, 256>>>(o, Wp_l, bp + l * D_MODEL, h, h,
                                                        ROWS, D_MODEL, D_MODEL, D_MODEL);

        ln_kernel<true><<<ROWS, 256>>>(h, ln2_w + l * D_MODEL, ln2_b + l * D_MODEL,
                                       lnfc_w + l * D_MODEL, lnfc_b + l * D_MODEL, a);

        gemm_kernel<true, false, false><<<gFF1, 256>>>(a, W1_l, b1 + l * D_FF, nullptr, m,
                                                       ROWS, D_FF, D_MODEL, D_FF);
        gemm_kernel<false, true, false><<<gProj, 256>>>(m, W2_l, b2 + l * D_MODEL, h, h,
                                                        ROWS, D_MODEL, D_FF, D_MODEL);
    }

    ln_kernel<false><<<ROWS, 256>>>(h, lnf_w, lnf_b, nullptr, nullptr, a);
    gemm_kernel<false, false, false><<<gHead, 256>>>(a, whp, bh, nullptr, out,
                                                     ROWS, VOCAB_P, D_MODEL, VOCAB);
}